// round 3
// baseline (speedup 1.0000x reference)
#include <cuda_runtime.h>
#include <cstddef>

// Problem constants
#define B_   4
#define L_   4096
#define E_   1024
#define H_   16
#define D_   64
#define C_   128          // chunk length
#define NC_  (L_ / C_)    // 32 chunks
#define MTOT (B_ * L_)    // 16384 rows
#define EPS_ 1e-5f

// ---------------------------------------------------------------------------
// Scratch (no cudaMalloc allowed -> __device__ globals)
// ---------------------------------------------------------------------------
__device__ float g_phi_q[(size_t)B_ * L_ * E_];
__device__ float g_phi_k[(size_t)B_ * L_ * E_];
__device__ float g_v    [(size_t)B_ * L_ * E_];
__device__ float g_attn [(size_t)B_ * L_ * E_];
__device__ float g_S[(size_t)B_ * H_ * NC_ * D_ * D_];  // chunk states (then excl. prefix)
__device__ float g_z[(size_t)B_ * H_ * NC_ * D_];       // chunk z      (then excl. prefix)

// ---------------------------------------------------------------------------
// SGEMM: C[M,N] = A[M,K] @ B[N,K]^T  (both operands K-contiguous, torch Linear)
// EPI: 0 = none, 1 = elu(x)+1, 2 = +bias
// ---------------------------------------------------------------------------
#define BM 128
#define BN 128
#define BK 8
#define TM 8
#define TN 8

template <int EPI>
__global__ __launch_bounds__(256, 2)
void sgemm_kernel(const float* __restrict__ A, const float* __restrict__ Bm,
                  const float* __restrict__ bias, float* __restrict__ Cmat,
                  int M, int N, int K)
{
    __shared__ float As[BK][BM];
    __shared__ float Bs[BK][BN];

    const int tid  = threadIdx.x;                 // 256 threads
    const int brow = blockIdx.y, bcol = blockIdx.x;

    const float* Ab = A  + (size_t)brow * BM * K;
    const float* Bb = Bm + (size_t)bcol * BN * K;

    const int lrow = tid >> 1;            // 0..127
    const int lc4  = (tid & 1) << 2;      // 0 or 4

    const int ty = tid >> 4;              // 0..15
    const int tx = tid & 15;              // 0..15

    float acc[TM][TN];
#pragma unroll
    for (int i = 0; i < TM; i++)
#pragma unroll
        for (int j = 0; j < TN; j++) acc[i][j] = 0.f;

#pragma unroll 4
    for (int kt = 0; kt < K; kt += BK) {
        float4 av = *(const float4*)(Ab + (size_t)lrow * K + kt + lc4);
        float4 bv = *(const float4*)(Bb + (size_t)lrow * K + kt + lc4);
        As[lc4 + 0][lrow] = av.x; As[lc4 + 1][lrow] = av.y;
        As[lc4 + 2][lrow] = av.z; As[lc4 + 3][lrow] = av.w;
        Bs[lc4 + 0][lrow] = bv.x; Bs[lc4 + 1][lrow] = bv.y;
        Bs[lc4 + 2][lrow] = bv.z; Bs[lc4 + 3][lrow] = bv.w;
        __syncthreads();

#pragma unroll
        for (int k = 0; k < BK; k++) {
            float a[TM], b[TN];
#pragma unroll
            for (int i = 0; i < TM; i++) a[i] = As[k][ty * TM + i];
#pragma unroll
            for (int j = 0; j < TN; j++) b[j] = Bs[k][tx * TN + j];
#pragma unroll
            for (int i = 0; i < TM; i++)
#pragma unroll
                for (int j = 0; j < TN; j++) acc[i][j] += a[i] * b[j];
        }
        __syncthreads();
    }

#pragma unroll
    for (int i = 0; i < TM; i++) {
        const int row = brow * BM + ty * TM + i;
#pragma unroll
        for (int j = 0; j < TN; j++) {
            const int col = bcol * BN + tx * TN + j;
            float v = acc[i][j];
            if (EPI == 1) v = (v > 0.f) ? (v + 1.f) : expf(v);   // elu(x)+1
            if (EPI == 2) v += bias[col];
            Cmat[(size_t)row * N + col] = v;
        }
    }
}

// ---------------------------------------------------------------------------
// Chunk-local states: S_loc[b,h,c] = phi_k_chunk^T @ V_chunk  (DxD),
//                     z_loc = colsum(phi_k_chunk)
// grid (NC_, H_, B_), 256 threads, 64KB dyn smem
// ---------------------------------------------------------------------------
__global__ __launch_bounds__(256)
void chunk_local_kernel(const float* __restrict__ pk, const float* __restrict__ vv,
                        float* __restrict__ Sloc, float* __restrict__ zloc)
{
    extern __shared__ float sm[];
    float* Pks = sm;                 // [C_][D_]
    float* Vs  = sm + C_ * D_;       // [C_][D_]

    const int c = blockIdx.x, h = blockIdx.y, b = blockIdx.z;
    const size_t base = ((size_t)b * L_ + (size_t)c * C_) * E_ + (size_t)h * D_;
    const float* pkb = pk + base;
    const float* vb  = vv + base;

    for (int i = threadIdx.x; i < C_ * D_ / 4; i += 256) {
        const int row = i >> 4;           // 16 float4 per row of 64
        const int c4  = (i & 15) << 2;
        *(float4*)&Pks[row * D_ + c4] = *(const float4*)(pkb + (size_t)row * E_ + c4);
        *(float4*)&Vs [row * D_ + c4] = *(const float4*)(vb  + (size_t)row * E_ + c4);
    }
    __syncthreads();

    const int ty = threadIdx.x >> 4, tx = threadIdx.x & 15;   // 16x16, 4x4 each
    float acc[4][4];
#pragma unroll
    for (int i = 0; i < 4; i++)
#pragma unroll
        for (int j = 0; j < 4; j++) acc[i][j] = 0.f;

#pragma unroll 4
    for (int t = 0; t < C_; t++) {
        float a[4], bb[4];
#pragma unroll
        for (int i = 0; i < 4; i++) a[i]  = Pks[t * D_ + ty * 4 + i];
#pragma unroll
        for (int j = 0; j < 4; j++) bb[j] = Vs [t * D_ + tx * 4 + j];
#pragma unroll
        for (int i = 0; i < 4; i++)
#pragma unroll
            for (int j = 0; j < 4; j++) acc[i][j] += a[i] * bb[j];
    }

    float* Sout = Sloc + ((((size_t)b * H_ + h) * NC_ + c) * D_ * D_);
#pragma unroll
    for (int i = 0; i < 4; i++)
#pragma unroll
        for (int j = 0; j < 4; j++)
            Sout[(ty * 4 + i) * D_ + tx * 4 + j] = acc[i][j];

    if (threadIdx.x < D_) {
        float s = 0.f;
#pragma unroll 8
        for (int t = 0; t < C_; t++) s += Pks[t * D_ + threadIdx.x];
        zloc[(((size_t)b * H_ + h) * NC_ + c) * D_ + threadIdx.x] = s;
    }
}

// ---------------------------------------------------------------------------
// Exclusive prefix over chunks, in place. grid(B_*H_), 256 threads.
// ---------------------------------------------------------------------------
__global__ __launch_bounds__(256)
void prefix_kernel(float* __restrict__ S, float* __restrict__ z)
{
    const int bh = blockIdx.x;
    float* Sb = S + (size_t)bh * NC_ * D_ * D_;
    float* zb = z + (size_t)bh * NC_ * D_;

    // D_*D_ = 4096 floats = 1024 float4; 256 threads -> 4 float4 each
    for (int i = threadIdx.x; i < D_ * D_ / 4; i += 256) {
        float4 run = make_float4(0.f, 0.f, 0.f, 0.f);
        for (int c = 0; c < NC_; c++) {
            float4* p = (float4*)&Sb[(size_t)c * D_ * D_ + i * 4];
            float4 loc = *p;
            *p = run;
            run.x += loc.x; run.y += loc.y; run.z += loc.z; run.w += loc.w;
        }
    }
    for (int i = threadIdx.x; i < D_; i += 256) {
        float run = 0.f;
        for (int c = 0; c < NC_; c++) {
            const float loc = zb[(size_t)c * D_ + i];
            zb[(size_t)c * D_ + i] = run;
            run += loc;
        }
    }
}

// ---------------------------------------------------------------------------
// Chunk output:
//   M = causal(phi_q @ phi_k^T)             (128x128)
//   den_t = phi_q_t . z_pref + rowsum(M_t) + EPS
//   O = (phi_q @ S_pref + M @ V) / den
// grid (NC_, H_, B_), 256 threads, ~182KB dyn smem
// ---------------------------------------------------------------------------
#define SM4_FLOATS (64*129 + 64*129 + 128*64 + 64*64 + 64 + 128*129 + 128)

__global__ __launch_bounds__(256)
void chunk_out_kernel(const float* __restrict__ pq, const float* __restrict__ pk,
                      const float* __restrict__ vv, const float* __restrict__ S,
                      const float* __restrict__ z, float* __restrict__ attn)
{
    extern __shared__ float sm[];
    float* PqT = sm;                       // [D_][C_+1] k-major
    float* PkT = PqT + 64 * 129;           // [D_][C_+1]
    float* Vs  = PkT + 64 * 129;           // [C_][D_]
    float* Sp  = Vs + 128 * 64;            // [D_][D_]
    float* zp  = Sp + 64 * 64;             // [D_]
    float* Ms  = zp + 64;                  // [C_][C_+1]
    float* rs  = Ms + 128 * 129;           // [C_] 1/den

    const int c = blockIdx.x, h = blockIdx.y, b = blockIdx.z;
    const size_t base = ((size_t)b * L_ + (size_t)c * C_) * E_ + (size_t)h * D_;
    const float* pqb = pq + base;
    const float* pkb = pk + base;
    const float* vb  = vv + base;

    for (int i = threadIdx.x; i < C_ * D_ / 4; i += 256) {
        const int row = i >> 4;
        const int c4  = (i & 15) << 2;
        float4 qv = *(const float4*)(pqb + (size_t)row * E_ + c4);
        float4 kv = *(const float4*)(pkb + (size_t)row * E_ + c4);
        float4 wv = *(const float4*)(vb  + (size_t)row * E_ + c4);
        PqT[(c4 + 0) * 129 + row] = qv.x; PqT[(c4 + 1) * 129 + row] = qv.y;
        PqT[(c4 + 2) * 129 + row] = qv.z; PqT[(c4 + 3) * 129 + row] = qv.w;
        PkT[(c4 + 0) * 129 + row] = kv.x; PkT[(c4 + 1) * 129 + row] = kv.y;
        PkT[(c4 + 2) * 129 + row] = kv.z; PkT[(c4 + 3) * 129 + row] = kv.w;
        *(float4*)&Vs[row * D_ + c4] = wv;
    }
    {
        const float* Sb = S + (((size_t)b * H_ + h) * NC_ + c) * D_ * D_;
        for (int i = threadIdx.x; i < D_ * D_ / 4; i += 256)
            *(float4*)&Sp[i * 4] = *(const float4*)(Sb + (size_t)i * 4);
        if (threadIdx.x < D_ / 4) {
            const float* zbp = z + (((size_t)b * H_ + h) * NC_ + c) * D_;
            *(float4*)&zp[threadIdx.x * 4] = *(const float4*)(zbp + threadIdx.x * 4);
        }
    }
    __syncthreads();

    const int ty = threadIdx.x >> 4, tx = threadIdx.x & 15;

    // ---- phase 1: scores, causal mask -------------------------------------
    {
        float acc[8][8];
#pragma unroll
        for (int i = 0; i < 8; i++)
#pragma unroll
            for (int j = 0; j < 8; j++) acc[i][j] = 0.f;

#pragma unroll 4
        for (int k = 0; k < D_; k++) {
            float a[8], bb[8];
#pragma unroll
            for (int i = 0; i < 8; i++) a[i]  = PqT[k * 129 + ty * 8 + i];
#pragma unroll
            for (int j = 0; j < 8; j++) bb[j] = PkT[k * 129 + tx * 8 + j];
#pragma unroll
            for (int i = 0; i < 8; i++)
#pragma unroll
                for (int j = 0; j < 8; j++) acc[i][j] += a[i] * bb[j];
        }
#pragma unroll
        for (int i = 0; i < 8; i++) {
            const int t = ty * 8 + i;
#pragma unroll
            for (int j = 0; j < 8; j++) {
                const int s = tx * 8 + j;
                Ms[t * 129 + s] = (s <= t) ? acc[i][j] : 0.f;
            }
        }
    }
    __syncthreads();

    // ---- phase 2: denominators (upper triangle already zeroed) ------------
    if (threadIdx.x < C_) {
        const int t = threadIdx.x;
        float ssum = 0.f;
#pragma unroll 8
        for (int j = 0; j < C_; j++) ssum += Ms[t * 129 + j];
        float dq = 0.f;
#pragma unroll 8
        for (int k = 0; k < D_; k++) dq += PqT[k * 129 + t] * zp[k];
        rs[t] = 1.f / (ssum + dq + EPS_);
    }
    __syncthreads();

    // ---- phase 3: outputs (8 rows x 4 cols per thread) --------------------
    {
        float acc[8][4];
#pragma unroll
        for (int i = 0; i < 8; i++)
#pragma unroll
            for (int j = 0; j < 4; j++) acc[i][j] = 0.f;

#pragma unroll 4
        for (int k = 0; k < D_; k++) {
            float a[8], bb[4];
#pragma unroll
            for (int i = 0; i < 8; i++) a[i]  = PqT[k * 129 + ty * 8 + i];
#pragma unroll
            for (int j = 0; j < 4; j++) bb[j] = Sp[k * D_ + tx * 4 + j];
#pragma unroll
            for (int i = 0; i < 8; i++)
#pragma unroll
                for (int j = 0; j < 4; j++) acc[i][j] += a[i] * bb[j];
        }
#pragma unroll 4
        for (int s = 0; s < C_; s++) {
            float a[8], bb[4];
#pragma unroll
            for (int i = 0; i < 8; i++) a[i]  = Ms[(ty * 8 + i) * 129 + s];
#pragma unroll
            for (int j = 0; j < 4; j++) bb[j] = Vs[s * D_ + tx * 4 + j];
#pragma unroll
            for (int i = 0; i < 8; i++)
#pragma unroll
                for (int j = 0; j < 4; j++) acc[i][j] += a[i] * bb[j];
        }

        float* ob = attn + base;
#pragma unroll
        for (int i = 0; i < 8; i++) {
            const float r = rs[ty * 8 + i];
            float4 o;
            o.x = acc[i][0] * r; o.y = acc[i][1] * r;
            o.z = acc[i][2] * r; o.w = acc[i][3] * r;
            *(float4*)(ob + (size_t)(ty * 8 + i) * E_ + tx * 4) = o;
        }
    }
}

// ---------------------------------------------------------------------------
// Launch
// ---------------------------------------------------------------------------
extern "C" void kernel_launch(void* const* d_in, const int* in_sizes, int n_in,
                              void* d_out, int out_size)
{
    const float* x  = (const float*)d_in[0];
    const float* Wq = (const float*)d_in[1];
    const float* Wk = (const float*)d_in[2];
    const float* Wv = (const float*)d_in[3];
    const float* Wo = (const float*)d_in[4];
    const float* bo = (const float*)d_in[5];
    float* out = (float*)d_out;

    float *phi_q, *phi_k, *vbuf, *attn, *Sb, *zb;
    cudaGetSymbolAddress((void**)&phi_q, g_phi_q);
    cudaGetSymbolAddress((void**)&phi_k, g_phi_k);
    cudaGetSymbolAddress((void**)&vbuf,  g_v);
    cudaGetSymbolAddress((void**)&attn,  g_attn);
    cudaGetSymbolAddress((void**)&Sb,    g_S);
    cudaGetSymbolAddress((void**)&zb,    g_z);

    const int sm_local = 2 * C_ * D_ * (int)sizeof(float);         // 64 KB
    const int sm_out   = SM4_FLOATS * (int)sizeof(float);          // ~182 KB
    (void)cudaFuncSetAttribute(chunk_local_kernel,
                               cudaFuncAttributeMaxDynamicSharedMemorySize, sm_local);
    (void)cudaFuncSetAttribute(chunk_out_kernel,
                               cudaFuncAttributeMaxDynamicSharedMemorySize, sm_out);

    dim3 gg(E_ / BN, MTOT / BM), gb(256);

    // q/k projections with fused elu+1; v plain
    sgemm_kernel<1><<<gg, gb>>>(x, Wq, nullptr, phi_q, MTOT, E_, E_);
    sgemm_kernel<1><<<gg, gb>>>(x, Wk, nullptr, phi_k, MTOT, E_, E_);
    sgemm_kernel<0><<<gg, gb>>>(x, Wv, nullptr, vbuf,  MTOT, E_, E_);

    dim3 gc(NC_, H_, B_);
    chunk_local_kernel<<<gc, 256, sm_local>>>(phi_k, vbuf, Sb, zb);
    prefix_kernel<<<B_ * H_, 256>>>(Sb, zb);
    chunk_out_kernel<<<gc, 256, sm_out>>>(phi_q, phi_k, vbuf, Sb, zb, attn);

    // output projection + bias
    sgemm_kernel<2><<<gg, gb>>>(attn, Wo, bo, out, MTOT, E_, E_);
}

// round 5
// speedup vs baseline: 2.1940x; 2.1940x over previous
#include <cuda_runtime.h>
#include <cuda_bf16.h>
#include <cstdint>
#include <cstddef>

// Problem constants
#define B_   4
#define L_   4096
#define E_   1024
#define H_   16
#define D_   64
#define C_   128          // chunk length
#define NC_  (L_ / C_)    // 32 chunks
#define MTOT (B_ * L_)    // 16384 rows
#define EPS_ 1e-5f

// ---------------------------------------------------------------------------
// Scratch (no cudaMalloc allowed -> __device__ globals)
// ---------------------------------------------------------------------------
__device__ float g_phi_q[(size_t)B_ * L_ * E_];
__device__ float g_phi_k[(size_t)B_ * L_ * E_];
__device__ float g_v    [(size_t)B_ * L_ * E_];
__device__ float g_S[(size_t)B_ * H_ * NC_ * D_ * D_];
__device__ float g_z[(size_t)B_ * H_ * NC_ * D_];

// bf16 split buffers
__device__ __nv_bfloat16 g_x_hi[(size_t)MTOT * E_];
__device__ __nv_bfloat16 g_x_lo[(size_t)MTOT * E_];
__device__ __nv_bfloat16 g_attn_hi[(size_t)MTOT * E_];
__device__ __nv_bfloat16 g_attn_lo[(size_t)MTOT * E_];
__device__ __nv_bfloat16 g_w_hi[4][(size_t)E_ * E_];
__device__ __nv_bfloat16 g_w_lo[4][(size_t)E_ * E_];

// ---------------------------------------------------------------------------
// Split fp32 -> bf16 hi + bf16 lo   (x = hi + lo, lo captures next 8 bits)
// ---------------------------------------------------------------------------
__global__ __launch_bounds__(256)
void split_kernel(const float* __restrict__ in, __nv_bfloat16* __restrict__ hi,
                  __nv_bfloat16* __restrict__ lo, int n4)
{
    int i = blockIdx.x * 256 + threadIdx.x;
    if (i >= n4) return;
    float4 v = ((const float4*)in)[i];
    __nv_bfloat16 h0 = __float2bfloat16(v.x);
    __nv_bfloat16 h1 = __float2bfloat16(v.y);
    __nv_bfloat16 h2 = __float2bfloat16(v.z);
    __nv_bfloat16 h3 = __float2bfloat16(v.w);
    __nv_bfloat16 l0 = __float2bfloat16(v.x - __bfloat162float(h0));
    __nv_bfloat16 l1 = __float2bfloat16(v.y - __bfloat162float(h1));
    __nv_bfloat16 l2 = __float2bfloat16(v.z - __bfloat162float(h2));
    __nv_bfloat16 l3 = __float2bfloat16(v.w - __bfloat162float(h3));
    union { __nv_bfloat16 b[4]; uint2 u; } ph, pl;
    ph.b[0] = h0; ph.b[1] = h1; ph.b[2] = h2; ph.b[3] = h3;
    pl.b[0] = l0; pl.b[1] = l1; pl.b[2] = l2; pl.b[3] = l3;
    ((uint2*)hi)[i] = ph.u;
    ((uint2*)lo)[i] = pl.u;
}

// ---------------------------------------------------------------------------
// Tensor-core GEMM with bf16 2-term split:
//   C[M,N] = (Ahi+Alo)[M,K] @ (Bhi+Blo)[N,K]^T  ~= hi*hi + hi*lo + lo*hi
// Block 128x128, K-tile 32, 8 warps (4m x 2n), warp tile 32x64.
// EPI: 0 = none, 1 = elu(x)+1, 2 = +bias
// ---------------------------------------------------------------------------
#define SROW 40                       // padded row length (bf16) -> 80B, conflict-free
#define STAGE_ELEMS (4 * 128 * SROW)  // Ahi, Alo, Bhi, Blo per stage
#define GEMM_SMEM (2 * STAGE_ELEMS * 2)  // bytes

__device__ __forceinline__ void mma_bf16(float* c, const uint32_t* a, const uint32_t* b)
{
    asm volatile(
        "mma.sync.aligned.m16n8k16.row.col.f32.bf16.bf16.f32 "
        "{%0,%1,%2,%3}, {%4,%5,%6,%7}, {%8,%9}, {%0,%1,%2,%3};\n"
        : "+f"(c[0]), "+f"(c[1]), "+f"(c[2]), "+f"(c[3])
        : "r"(a[0]), "r"(a[1]), "r"(a[2]), "r"(a[3]), "r"(b[0]), "r"(b[1]));
}

__device__ __forceinline__ void cp16(__nv_bfloat16* dst, const __nv_bfloat16* src)
{
    uint32_t d = (uint32_t)__cvta_generic_to_shared(dst);
    asm volatile("cp.async.cg.shared.global [%0], [%1], 16;\n" :: "r"(d), "l"(src));
}
__device__ __forceinline__ void cp_commit() { asm volatile("cp.async.commit_group;\n"); }
__device__ __forceinline__ void cp_wait1()  { asm volatile("cp.async.wait_group 1;\n"); }
__device__ __forceinline__ void cp_wait0()  { asm volatile("cp.async.wait_group 0;\n"); }

template <int EPI>
__global__ __launch_bounds__(256, 2)
void gemm_bf16split(const __nv_bfloat16* __restrict__ Ahi, const __nv_bfloat16* __restrict__ Alo,
                    const __nv_bfloat16* __restrict__ Bhi, const __nv_bfloat16* __restrict__ Blo,
                    const float* __restrict__ bias, float* __restrict__ Cmat,
                    int M, int N, int K)
{
    extern __shared__ __nv_bfloat16 smem[];

    const int tid  = threadIdx.x;
    const int bm   = blockIdx.y * 128;
    const int bn   = blockIdx.x * 128;
    const int warp = tid >> 5, lane = tid & 31;
    const int wm   = (warp & 3) * 32;
    const int wn   = (warp >> 2) * 64;
    const int gid  = lane >> 2;     // 0..7
    const int tig  = lane & 3;      // 0..3

    const int KT = K / 32;

    __nv_bfloat16* stage0 = smem;
    __nv_bfloat16* stage1 = smem + STAGE_ELEMS;

    // cp.async issue of one k-tile into stage s
    auto issue = [&](int kt, int s) {
        __nv_bfloat16* sAh = s ? stage1 : stage0;
        __nv_bfloat16* sAl = sAh + 128 * SROW;
        __nv_bfloat16* sBh = sAl + 128 * SROW;
        __nv_bfloat16* sBl = sBh + 128 * SROW;
        const int kbase = kt * 32;
#pragma unroll
        for (int c = 0; c < 2; c++) {
            int q   = tid + c * 256;         // 0..511
            int row = q >> 2;
            int kc  = (q & 3) << 3;          // 0,8,16,24
            const size_t ga = (size_t)(bm + row) * K + kbase + kc;
            const size_t gb = (size_t)(bn + row) * K + kbase + kc;
            cp16(sAh + row * SROW + kc, Ahi + ga);
            cp16(sAl + row * SROW + kc, Alo + ga);
            cp16(sBh + row * SROW + kc, Bhi + gb);
            cp16(sBl + row * SROW + kc, Blo + gb);
        }
        cp_commit();
    };

    float acc[2][8][4];
#pragma unroll
    for (int mi = 0; mi < 2; mi++)
#pragma unroll
        for (int ni = 0; ni < 8; ni++)
#pragma unroll
            for (int j = 0; j < 4; j++) acc[mi][ni][j] = 0.f;

    issue(0, 0);
    issue(1, 1);

    for (int kt = 0; kt < KT; kt++) {
        if (kt + 1 < KT) cp_wait1(); else cp_wait0();
        __syncthreads();

        const int s = kt & 1;
        const __nv_bfloat16* sAh = s ? stage1 : stage0;
        const __nv_bfloat16* sAl = sAh + 128 * SROW;
        const __nv_bfloat16* sBh = sAl + 128 * SROW;
        const __nv_bfloat16* sBl = sBh + 128 * SROW;

#pragma unroll
        for (int ks = 0; ks < 2; ks++) {
            const int k0 = ks * 16 + tig * 2;
            uint32_t ahi[2][4], alo[2][4];
#pragma unroll
            for (int mi = 0; mi < 2; mi++) {
                const int r = wm + mi * 16 + gid;
                ahi[mi][0] = *(const uint32_t*)(sAh + r * SROW + k0);
                ahi[mi][1] = *(const uint32_t*)(sAh + (r + 8) * SROW + k0);
                ahi[mi][2] = *(const uint32_t*)(sAh + r * SROW + k0 + 8);
                ahi[mi][3] = *(const uint32_t*)(sAh + (r + 8) * SROW + k0 + 8);
                alo[mi][0] = *(const uint32_t*)(sAl + r * SROW + k0);
                alo[mi][1] = *(const uint32_t*)(sAl + (r + 8) * SROW + k0);
                alo[mi][2] = *(const uint32_t*)(sAl + r * SROW + k0 + 8);
                alo[mi][3] = *(const uint32_t*)(sAl + (r + 8) * SROW + k0 + 8);
            }
#pragma unroll
            for (int ni = 0; ni < 8; ni++) {
                const int n = wn + ni * 8 + gid;
                uint32_t bh[2], bl[2];
                bh[0] = *(const uint32_t*)(sBh + n * SROW + k0);
                bh[1] = *(const uint32_t*)(sBh + n * SROW + k0 + 8);
                bl[0] = *(const uint32_t*)(sBl + n * SROW + k0);
                bl[1] = *(const uint32_t*)(sBl + n * SROW + k0 + 8);
#pragma unroll
                for (int mi = 0; mi < 2; mi++) {
                    mma_bf16(acc[mi][ni], ahi[mi], bh);
                    mma_bf16(acc[mi][ni], ahi[mi], bl);
                    mma_bf16(acc[mi][ni], alo[mi], bh);
                }
            }
        }
        __syncthreads();
        if (kt + 2 < KT) issue(kt + 2, s);
    }

    // Epilogue: c0,c1 -> (row, col..col+1); c2,c3 -> (row+8, col..col+1)
#pragma unroll
    for (int mi = 0; mi < 2; mi++) {
#pragma unroll
        for (int ni = 0; ni < 8; ni++) {
            const int row = bm + wm + mi * 16 + gid;
            const int col = bn + wn + ni * 8 + tig * 2;
            float v0 = acc[mi][ni][0], v1 = acc[mi][ni][1];
            float v2 = acc[mi][ni][2], v3 = acc[mi][ni][3];
            if (EPI == 1) {
                v0 = (v0 > 0.f) ? (v0 + 1.f) : expf(v0);
                v1 = (v1 > 0.f) ? (v1 + 1.f) : expf(v1);
                v2 = (v2 > 0.f) ? (v2 + 1.f) : expf(v2);
                v3 = (v3 > 0.f) ? (v3 + 1.f) : expf(v3);
            }
            if (EPI == 2) {
                v0 += bias[col]; v1 += bias[col + 1];
                v2 += bias[col]; v3 += bias[col + 1];
            }
            *(float2*)(Cmat + (size_t)row * N + col)       = make_float2(v0, v1);
            *(float2*)(Cmat + (size_t)(row + 8) * N + col) = make_float2(v2, v3);
        }
    }
}

// ---------------------------------------------------------------------------
// Chunk-local states: S_loc[b,h,c] = phi_k_chunk^T @ V_chunk, z_loc = colsum
// ---------------------------------------------------------------------------
__global__ __launch_bounds__(256)
void chunk_local_kernel(const float* __restrict__ pk, const float* __restrict__ vv,
                        float* __restrict__ Sloc, float* __restrict__ zloc)
{
    extern __shared__ float sm[];
    float* Pks = sm;                 // [C_][D_]
    float* Vs  = sm + C_ * D_;       // [C_][D_]

    const int c = blockIdx.x, h = blockIdx.y, b = blockIdx.z;
    const size_t base = ((size_t)b * L_ + (size_t)c * C_) * E_ + (size_t)h * D_;
    const float* pkb = pk + base;
    const float* vb  = vv + base;

    for (int i = threadIdx.x; i < C_ * D_ / 4; i += 256) {
        const int row = i >> 4;
        const int c4  = (i & 15) << 2;
        *(float4*)&Pks[row * D_ + c4] = *(const float4*)(pkb + (size_t)row * E_ + c4);
        *(float4*)&Vs [row * D_ + c4] = *(const float4*)(vb  + (size_t)row * E_ + c4);
    }
    __syncthreads();

    const int ty = threadIdx.x >> 4, tx = threadIdx.x & 15;
    float acc[4][4];
#pragma unroll
    for (int i = 0; i < 4; i++)
#pragma unroll
        for (int j = 0; j < 4; j++) acc[i][j] = 0.f;

#pragma unroll 4
    for (int t = 0; t < C_; t++) {
        float a[4], bb[4];
#pragma unroll
        for (int i = 0; i < 4; i++) a[i]  = Pks[t * D_ + ty * 4 + i];
#pragma unroll
        for (int j = 0; j < 4; j++) bb[j] = Vs [t * D_ + tx * 4 + j];
#pragma unroll
        for (int i = 0; i < 4; i++)
#pragma unroll
            for (int j = 0; j < 4; j++) acc[i][j] += a[i] * bb[j];
    }

    float* Sout = Sloc + ((((size_t)b * H_ + h) * NC_ + c) * D_ * D_);
#pragma unroll
    for (int i = 0; i < 4; i++)
#pragma unroll
        for (int j = 0; j < 4; j++)
            Sout[(ty * 4 + i) * D_ + tx * 4 + j] = acc[i][j];

    if (threadIdx.x < D_) {
        float s = 0.f;
#pragma unroll 8
        for (int t = 0; t < C_; t++) s += Pks[t * D_ + threadIdx.x];
        zloc[(((size_t)b * H_ + h) * NC_ + c) * D_ + threadIdx.x] = s;
    }
}

// ---------------------------------------------------------------------------
// Exclusive prefix over chunks, in place.
// ---------------------------------------------------------------------------
__global__ __launch_bounds__(256)
void prefix_kernel(float* __restrict__ S, float* __restrict__ z)
{
    const int bh = blockIdx.x;
    float* Sb = S + (size_t)bh * NC_ * D_ * D_;
    float* zb = z + (size_t)bh * NC_ * D_;

    for (int i = threadIdx.x; i < D_ * D_ / 4; i += 256) {
        float4 run = make_float4(0.f, 0.f, 0.f, 0.f);
        for (int c = 0; c < NC_; c++) {
            float4* p = (float4*)&Sb[(size_t)c * D_ * D_ + i * 4];
            float4 loc = *p;
            *p = run;
            run.x += loc.x; run.y += loc.y; run.z += loc.z; run.w += loc.w;
        }
    }
    for (int i = threadIdx.x; i < D_; i += 256) {
        float run = 0.f;
        for (int c = 0; c < NC_; c++) {
            const float loc = zb[(size_t)c * D_ + i];
            zb[(size_t)c * D_ + i] = run;
            run += loc;
        }
    }
}

// ---------------------------------------------------------------------------
// Chunk output -> writes attn as bf16 hi/lo for the tensor-core out-proj.
// ---------------------------------------------------------------------------
#define SM4_FLOATS (64*129 + 64*129 + 128*64 + 64*64 + 64 + 128*129 + 128)

__global__ __launch_bounds__(256)
void chunk_out_kernel(const float* __restrict__ pq, const float* __restrict__ pk,
                      const float* __restrict__ vv, const float* __restrict__ S,
                      const float* __restrict__ z,
                      __nv_bfloat16* __restrict__ attn_hi,
                      __nv_bfloat16* __restrict__ attn_lo)
{
    extern __shared__ float sm[];
    float* PqT = sm;                       // [D_][C_+1] k-major
    float* PkT = PqT + 64 * 129;           // [D_][C_+1]
    float* Vs  = PkT + 64 * 129;           // [C_][D_]
    float* Sp  = Vs + 128 * 64;            // [D_][D_]
    float* zp  = Sp + 64 * 64;             // [D_]
    float* Ms  = zp + 64;                  // [C_][C_+1]
    float* rs  = Ms + 128 * 129;           // [C_] 1/den

    const int c = blockIdx.x, h = blockIdx.y, b = blockIdx.z;
    const size_t base = ((size_t)b * L_ + (size_t)c * C_) * E_ + (size_t)h * D_;
    const float* pqb = pq + base;
    const float* pkb = pk + base;
    const float* vb  = vv + base;

    for (int i = threadIdx.x; i < C_ * D_ / 4; i += 256) {
        const int row = i >> 4;
        const int c4  = (i & 15) << 2;
        float4 qv = *(const float4*)(pqb + (size_t)row * E_ + c4);
        float4 kv = *(const float4*)(pkb + (size_t)row * E_ + c4);
        float4 wv = *(const float4*)(vb  + (size_t)row * E_ + c4);
        PqT[(c4 + 0) * 129 + row] = qv.x; PqT[(c4 + 1) * 129 + row] = qv.y;
        PqT[(c4 + 2) * 129 + row] = qv.z; PqT[(c4 + 3) * 129 + row] = qv.w;
        PkT[(c4 + 0) * 129 + row] = kv.x; PkT[(c4 + 1) * 129 + row] = kv.y;
        PkT[(c4 + 2) * 129 + row] = kv.z; PkT[(c4 + 3) * 129 + row] = kv.w;
        *(float4*)&Vs[row * D_ + c4] = wv;
    }
    {
        const float* Sb = S + (((size_t)b * H_ + h) * NC_ + c) * D_ * D_;
        for (int i = threadIdx.x; i < D_ * D_ / 4; i += 256)
            *(float4*)&Sp[i * 4] = *(const float4*)(Sb + (size_t)i * 4);
        if (threadIdx.x < D_ / 4) {
            const float* zbp = z + (((size_t)b * H_ + h) * NC_ + c) * D_;
            *(float4*)&zp[threadIdx.x * 4] = *(const float4*)(zbp + threadIdx.x * 4);
        }
    }
    __syncthreads();

    const int ty = threadIdx.x >> 4, tx = threadIdx.x & 15;

    // ---- phase 1: scores, causal mask -------------------------------------
    {
        float acc[8][8];
#pragma unroll
        for (int i = 0; i < 8; i++)
#pragma unroll
            for (int j = 0; j < 8; j++) acc[i][j] = 0.f;

#pragma unroll 4
        for (int k = 0; k < D_; k++) {
            float a[8], bb[8];
#pragma unroll
            for (int i = 0; i < 8; i++) a[i]  = PqT[k * 129 + ty * 8 + i];
#pragma unroll
            for (int j = 0; j < 8; j++) bb[j] = PkT[k * 129 + tx * 8 + j];
#pragma unroll
            for (int i = 0; i < 8; i++)
#pragma unroll
                for (int j = 0; j < 8; j++) acc[i][j] += a[i] * bb[j];
        }
#pragma unroll
        for (int i = 0; i < 8; i++) {
            const int t = ty * 8 + i;
#pragma unroll
            for (int j = 0; j < 8; j++) {
                const int s = tx * 8 + j;
                Ms[t * 129 + s] = (s <= t) ? acc[i][j] : 0.f;
            }
        }
    }
    __syncthreads();

    // ---- phase 2: denominators --------------------------------------------
    if (threadIdx.x < C_) {
        const int t = threadIdx.x;
        float ssum = 0.f;
#pragma unroll 8
        for (int j = 0; j < C_; j++) ssum += Ms[t * 129 + j];
        float dq = 0.f;
#pragma unroll 8
        for (int k = 0; k < D_; k++) dq += PqT[k * 129 + t] * zp[k];
        rs[t] = 1.f / (ssum + dq + EPS_);
    }
    __syncthreads();

    // ---- phase 3: outputs -------------------------------------------------
    {
        float acc[8][4];
#pragma unroll
        for (int i = 0; i < 8; i++)
#pragma unroll
            for (int j = 0; j < 4; j++) acc[i][j] = 0.f;

#pragma unroll 4
        for (int k = 0; k < D_; k++) {
            float a[8], bb[4];
#pragma unroll
            for (int i = 0; i < 8; i++) a[i]  = PqT[k * 129 + ty * 8 + i];
#pragma unroll
            for (int j = 0; j < 4; j++) bb[j] = Sp[k * D_ + tx * 4 + j];
#pragma unroll
            for (int i = 0; i < 8; i++)
#pragma unroll
                for (int j = 0; j < 4; j++) acc[i][j] += a[i] * bb[j];
        }
#pragma unroll 4
        for (int s = 0; s < C_; s++) {
            float a[8], bb[4];
#pragma unroll
            for (int i = 0; i < 8; i++) a[i]  = Ms[(ty * 8 + i) * 129 + s];
#pragma unroll
            for (int j = 0; j < 4; j++) bb[j] = Vs[s * D_ + tx * 4 + j];
#pragma unroll
            for (int i = 0; i < 8; i++)
#pragma unroll
                for (int j = 0; j < 4; j++) acc[i][j] += a[i] * bb[j];
        }

        __nv_bfloat16* obh = attn_hi + base;
        __nv_bfloat16* obl = attn_lo + base;
#pragma unroll
        for (int i = 0; i < 8; i++) {
            const float r = rs[ty * 8 + i];
            union { __nv_bfloat16 b[4]; uint2 u; } ph, pl;
#pragma unroll
            for (int j = 0; j < 4; j++) {
                float o = acc[i][j] * r;
                __nv_bfloat16 hbit = __float2bfloat16(o);
                ph.b[j] = hbit;
                pl.b[j] = __float2bfloat16(o - __bfloat162float(hbit));
            }
            const size_t off = (size_t)(ty * 8 + i) * E_ + tx * 4;
            *(uint2*)(obh + off) = ph.u;
            *(uint2*)(obl + off) = pl.u;
        }
    }
}

// ---------------------------------------------------------------------------
// Launch
// ---------------------------------------------------------------------------
extern "C" void kernel_launch(void* const* d_in, const int* in_sizes, int n_in,
                              void* d_out, int out_size)
{
    const float* x  = (const float*)d_in[0];
    const float* Wq = (const float*)d_in[1];
    const float* Wk = (const float*)d_in[2];
    const float* Wv = (const float*)d_in[3];
    const float* Wo = (const float*)d_in[4];
    const float* bo = (const float*)d_in[5];
    float* out = (float*)d_out;

    float *phi_q, *phi_k, *vbuf, *Sb, *zb;
    __nv_bfloat16 *xhi, *xlo, *ahi, *alo, *whi, *wlo;
    cudaGetSymbolAddress((void**)&phi_q, g_phi_q);
    cudaGetSymbolAddress((void**)&phi_k, g_phi_k);
    cudaGetSymbolAddress((void**)&vbuf,  g_v);
    cudaGetSymbolAddress((void**)&Sb,    g_S);
    cudaGetSymbolAddress((void**)&zb,    g_z);
    cudaGetSymbolAddress((void**)&xhi,   g_x_hi);
    cudaGetSymbolAddress((void**)&xlo,   g_x_lo);
    cudaGetSymbolAddress((void**)&ahi,   g_attn_hi);
    cudaGetSymbolAddress((void**)&alo,   g_attn_lo);
    cudaGetSymbolAddress((void**)&whi,   g_w_hi);
    cudaGetSymbolAddress((void**)&wlo,   g_w_lo);

    const int sm_local = 2 * C_ * D_ * (int)sizeof(float);
    const int sm_out   = SM4_FLOATS * (int)sizeof(float);
    (void)cudaFuncSetAttribute(chunk_local_kernel,
                               cudaFuncAttributeMaxDynamicSharedMemorySize, sm_local);
    (void)cudaFuncSetAttribute(chunk_out_kernel,
                               cudaFuncAttributeMaxDynamicSharedMemorySize, sm_out);
    (void)cudaFuncSetAttribute(gemm_bf16split<0>,
                               cudaFuncAttributeMaxDynamicSharedMemorySize, GEMM_SMEM);
    (void)cudaFuncSetAttribute(gemm_bf16split<1>,
                               cudaFuncAttributeMaxDynamicSharedMemorySize, GEMM_SMEM);
    (void)cudaFuncSetAttribute(gemm_bf16split<2>,
                               cudaFuncAttributeMaxDynamicSharedMemorySize, GEMM_SMEM);

    // ---- split inputs to bf16 hi/lo ----
    const int nx4 = (MTOT * E_) / 4;
    split_kernel<<<(nx4 + 255) / 256, 256>>>(x, xhi, xlo, nx4);
    const int nw4 = (E_ * E_) / 4;
    const size_t wsz = (size_t)E_ * E_;
    split_kernel<<<(nw4 + 255) / 256, 256>>>(Wq, whi + 0 * wsz, wlo + 0 * wsz, nw4);
    split_kernel<<<(nw4 + 255) / 256, 256>>>(Wk, whi + 1 * wsz, wlo + 1 * wsz, nw4);
    split_kernel<<<(nw4 + 255) / 256, 256>>>(Wv, whi + 2 * wsz, wlo + 2 * wsz, nw4);
    split_kernel<<<(nw4 + 255) / 256, 256>>>(Wo, whi + 3 * wsz, wlo + 3 * wsz, nw4);

    // ---- projections (tensor core) ----
    dim3 gg(E_ / 128, MTOT / 128), gb(256);
    gemm_bf16split<1><<<gg, gb, GEMM_SMEM>>>(xhi, xlo, whi + 0 * wsz, wlo + 0 * wsz,
                                             nullptr, phi_q, MTOT, E_, E_);
    gemm_bf16split<1><<<gg, gb, GEMM_SMEM>>>(xhi, xlo, whi + 1 * wsz, wlo + 1 * wsz,
                                             nullptr, phi_k, MTOT, E_, E_);
    gemm_bf16split<0><<<gg, gb, GEMM_SMEM>>>(xhi, xlo, whi + 2 * wsz, wlo + 2 * wsz,
                                             nullptr, vbuf, MTOT, E_, E_);

    // ---- chunked linear attention ----
    dim3 gc(NC_, H_, B_);
    chunk_local_kernel<<<gc, 256, sm_local>>>(phi_k, vbuf, Sb, zb);
    prefix_kernel<<<B_ * H_, 256>>>(Sb, zb);
    chunk_out_kernel<<<gc, 256, sm_out>>>(phi_q, phi_k, vbuf, Sb, zb, ahi, alo);

    // ---- output projection + bias (tensor core) ----
    gemm_bf16split<2><<<gg, gb, GEMM_SMEM>>>(ahi, alo, whi + 3 * wsz, wlo + 3 * wsz,
                                             bo, out, MTOT, E_, E_);
}

// round 6
// speedup vs baseline: 2.3633x; 1.0772x over previous
#include <cuda_runtime.h>
#include <cuda_bf16.h>
#include <cstdint>
#include <cstddef>

// Problem constants
#define B_   4
#define L_   4096
#define E_   1024
#define H_   16
#define D_   64
#define C_   128          // chunk length
#define NC_  (L_ / C_)    // 32 chunks
#define MTOT (B_ * L_)    // 16384 rows
#define EPS_ 1e-5f

// ---------------------------------------------------------------------------
// Scratch (no cudaMalloc allowed -> __device__ globals)
// ---------------------------------------------------------------------------
__device__ float g_phi_q[(size_t)B_ * L_ * E_];
__device__ float g_phi_k[(size_t)B_ * L_ * E_];
__device__ float g_v    [(size_t)B_ * L_ * E_];
__device__ float g_S[(size_t)B_ * H_ * NC_ * D_ * D_];
__device__ float g_z[(size_t)B_ * H_ * NC_ * D_];

// bf16 split buffers
__device__ __nv_bfloat16 g_x_hi[(size_t)MTOT * E_];
__device__ __nv_bfloat16 g_x_lo[(size_t)MTOT * E_];
__device__ __nv_bfloat16 g_attn_hi[(size_t)MTOT * E_];
__device__ __nv_bfloat16 g_attn_lo[(size_t)MTOT * E_];
__device__ __nv_bfloat16 g_w_hi[4][(size_t)E_ * E_];   // q,k,v contiguous = [3072][1024]
__device__ __nv_bfloat16 g_w_lo[4][(size_t)E_ * E_];

// ---------------------------------------------------------------------------
// Split fp32 -> bf16 hi + bf16 lo
// ---------------------------------------------------------------------------
__global__ __launch_bounds__(256)
void split_kernel(const float* __restrict__ in, __nv_bfloat16* __restrict__ hi,
                  __nv_bfloat16* __restrict__ lo, int n4)
{
    int i = blockIdx.x * 256 + threadIdx.x;
    if (i >= n4) return;
    float4 v = ((const float4*)in)[i];
    __nv_bfloat16 h0 = __float2bfloat16(v.x);
    __nv_bfloat16 h1 = __float2bfloat16(v.y);
    __nv_bfloat16 h2 = __float2bfloat16(v.z);
    __nv_bfloat16 h3 = __float2bfloat16(v.w);
    __nv_bfloat16 l0 = __float2bfloat16(v.x - __bfloat162float(h0));
    __nv_bfloat16 l1 = __float2bfloat16(v.y - __bfloat162float(h1));
    __nv_bfloat16 l2 = __float2bfloat16(v.z - __bfloat162float(h2));
    __nv_bfloat16 l3 = __float2bfloat16(v.w - __bfloat162float(h3));
    union { __nv_bfloat16 b[4]; uint2 u; } ph, pl;
    ph.b[0] = h0; ph.b[1] = h1; ph.b[2] = h2; ph.b[3] = h3;
    pl.b[0] = l0; pl.b[1] = l1; pl.b[2] = l2; pl.b[3] = l3;
    ((uint2*)hi)[i] = ph.u;
    ((uint2*)lo)[i] = pl.u;
}

// ---------------------------------------------------------------------------
// Tensor-core GEMM, bf16 2-term split (hi*hi + hi*lo + lo*hi), ldmatrix loads.
// Block 128x128, K-tile 32, 8 warps (4m x 2n), warp tile 32x64, 2-stage cp.async.
// MODE 0: single output + bias.  MODE 1: fused QKV (N=3072), elu+1 on q,k.
// ---------------------------------------------------------------------------
#define SROW 40
#define STAGE_ELEMS (4 * 128 * SROW)
#define GEMM_SMEM (2 * STAGE_ELEMS * 2)

__device__ __forceinline__ void mma_bf16(float* c, const uint32_t* a, const uint32_t* b)
{
    asm volatile(
        "mma.sync.aligned.m16n8k16.row.col.f32.bf16.bf16.f32 "
        "{%0,%1,%2,%3}, {%4,%5,%6,%7}, {%8,%9}, {%0,%1,%2,%3};\n"
        : "+f"(c[0]), "+f"(c[1]), "+f"(c[2]), "+f"(c[3])
        : "r"(a[0]), "r"(a[1]), "r"(a[2]), "r"(a[3]), "r"(b[0]), "r"(b[1]));
}

__device__ __forceinline__ void ldm_x4(uint32_t* r, uint32_t addr)
{
    asm volatile("ldmatrix.sync.aligned.m8n8.x4.shared.b16 {%0,%1,%2,%3}, [%4];\n"
                 : "=r"(r[0]), "=r"(r[1]), "=r"(r[2]), "=r"(r[3]) : "r"(addr));
}

__device__ __forceinline__ void cp16(__nv_bfloat16* dst, const __nv_bfloat16* src)
{
    uint32_t d = (uint32_t)__cvta_generic_to_shared(dst);
    asm volatile("cp.async.cg.shared.global [%0], [%1], 16;\n" :: "r"(d), "l"(src));
}
__device__ __forceinline__ void cp_commit() { asm volatile("cp.async.commit_group;\n"); }
__device__ __forceinline__ void cp_wait1()  { asm volatile("cp.async.wait_group 1;\n"); }
__device__ __forceinline__ void cp_wait0()  { asm volatile("cp.async.wait_group 0;\n"); }

template <int MODE>
__global__ __launch_bounds__(256, 2)
void gemm_bf16split(const __nv_bfloat16* __restrict__ Ahi, const __nv_bfloat16* __restrict__ Alo,
                    const __nv_bfloat16* __restrict__ Bhi, const __nv_bfloat16* __restrict__ Blo,
                    const float* __restrict__ bias,
                    float* __restrict__ out0, float* __restrict__ out1, float* __restrict__ out2,
                    int M, int N, int K)
{
    extern __shared__ __nv_bfloat16 smem[];

    const int tid  = threadIdx.x;
    const int bm   = blockIdx.y * 128;
    const int bn   = blockIdx.x * 128;
    const int warp = tid >> 5, lane = tid & 31;
    const int wm   = (warp & 3) * 32;
    const int wn   = (warp >> 2) * 64;
    const int gid  = lane >> 2;
    const int tig  = lane & 3;

    const int KT = K / 32;

    __nv_bfloat16* stage0 = smem;
    __nv_bfloat16* stage1 = smem + STAGE_ELEMS;
    const uint32_t st0s = (uint32_t)__cvta_generic_to_shared(stage0);
    const uint32_t st1s = st0s + STAGE_ELEMS * 2;
    const uint32_t ALO_OFF = 128 * SROW * 2;       // bytes: sAl after sAh
    const uint32_t BHI_OFF = 2 * 128 * SROW * 2;
    const uint32_t BLO_OFF = 3 * 128 * SROW * 2;

    // ldmatrix per-thread element offsets (within A / B planes)
    const int lidx = lane & 7;
    const int lmat = lane >> 3;
    // A x4: m0 rows r..r+7 @k0, m1 rows r+8.. @k0, m2 rows r..r+7 @k0+8, m3 rows r+8 @k0+8
    int aoff[2];
#pragma unroll
    for (int mi = 0; mi < 2; mi++)
        aoff[mi] = (wm + mi * 16 + ((lmat & 1) << 3) + lidx) * SROW + ((lmat >> 1) << 3);
    // B x4 for ni-pair p: m0 n0..7@k0, m1 n0..7@k0+8, m2 n8..15@k0, m3 n8..15@k0+8
    int boff[4];
#pragma unroll
    for (int p = 0; p < 4; p++)
        boff[p] = (wn + p * 16 + ((lmat >> 1) << 3) + lidx) * SROW + ((lmat & 1) << 3);

    // cp.async issue of one k-tile into stage s
    auto issue = [&](int kt, int s) {
        __nv_bfloat16* sAh = s ? stage1 : stage0;
        __nv_bfloat16* sAl = sAh + 128 * SROW;
        __nv_bfloat16* sBh = sAl + 128 * SROW;
        __nv_bfloat16* sBl = sBh + 128 * SROW;
        const int kbase = kt * 32;
#pragma unroll
        for (int c = 0; c < 2; c++) {
            int q   = tid + c * 256;
            int row = q >> 2;
            int kc  = (q & 3) << 3;
            const size_t ga = (size_t)(bm + row) * K + kbase + kc;
            const size_t gb = (size_t)(bn + row) * K + kbase + kc;
            cp16(sAh + row * SROW + kc, Ahi + ga);
            cp16(sAl + row * SROW + kc, Alo + ga);
            cp16(sBh + row * SROW + kc, Bhi + gb);
            cp16(sBl + row * SROW + kc, Blo + gb);
        }
        cp_commit();
    };

    float acc[2][8][4];
#pragma unroll
    for (int mi = 0; mi < 2; mi++)
#pragma unroll
        for (int ni = 0; ni < 8; ni++)
#pragma unroll
            for (int j = 0; j < 4; j++) acc[mi][ni][j] = 0.f;

    issue(0, 0);
    issue(1, 1);

    for (int kt = 0; kt < KT; kt++) {
        if (kt + 1 < KT) cp_wait1(); else cp_wait0();
        __syncthreads();

        const uint32_t sb = (kt & 1) ? st1s : st0s;

#pragma unroll
        for (int ks = 0; ks < 2; ks++) {
            const uint32_t kofs = (uint32_t)(ks * 16) * 2;   // bytes
            uint32_t ahi[2][4], alo[2][4];
#pragma unroll
            for (int mi = 0; mi < 2; mi++) {
                const uint32_t ab = sb + (uint32_t)aoff[mi] * 2 + kofs;
                ldm_x4(ahi[mi], ab);
                ldm_x4(alo[mi], ab + ALO_OFF);
            }
#pragma unroll
            for (int p = 0; p < 4; p++) {
                uint32_t bh4[4], bl4[4];
                const uint32_t bb = sb + BHI_OFF + (uint32_t)boff[p] * 2 + kofs;
                ldm_x4(bh4, bb);
                ldm_x4(bl4, bb + (BLO_OFF - BHI_OFF));
#pragma unroll
                for (int sub = 0; sub < 2; sub++) {
                    const uint32_t bh2[2] = { bh4[sub * 2], bh4[sub * 2 + 1] };
                    const uint32_t bl2[2] = { bl4[sub * 2], bl4[sub * 2 + 1] };
                    const int ni = p * 2 + sub;
#pragma unroll
                    for (int mi = 0; mi < 2; mi++) {
                        mma_bf16(acc[mi][ni], ahi[mi], bh2);
                        mma_bf16(acc[mi][ni], ahi[mi], bl2);
                        mma_bf16(acc[mi][ni], alo[mi], bh2);
                    }
                }
            }
        }
        __syncthreads();
        if (kt + 2 < KT) issue(kt + 2, kt & 1);
    }

    // Epilogue
    float* dst;
    int col_base, nOut;
    bool do_elu = false;
    if (MODE == 1) {
        const int seg = (int)blockIdx.x >> 3;            // 0=q 1=k 2=v
        dst = (seg == 0) ? out0 : (seg == 1) ? out1 : out2;
        col_base = ((int)blockIdx.x & 7) * 128;
        nOut = 1024;
        do_elu = (seg < 2);
    } else {
        dst = out0; col_base = bn; nOut = N;
    }

#pragma unroll
    for (int mi = 0; mi < 2; mi++) {
#pragma unroll
        for (int ni = 0; ni < 8; ni++) {
            const int row = bm + wm + mi * 16 + gid;
            const int col = col_base + wn + ni * 8 + tig * 2;
            float v0 = acc[mi][ni][0], v1 = acc[mi][ni][1];
            float v2 = acc[mi][ni][2], v3 = acc[mi][ni][3];
            if (MODE == 1) {
                if (do_elu) {
                    v0 = (v0 > 0.f) ? (v0 + 1.f) : expf(v0);
                    v1 = (v1 > 0.f) ? (v1 + 1.f) : expf(v1);
                    v2 = (v2 > 0.f) ? (v2 + 1.f) : expf(v2);
                    v3 = (v3 > 0.f) ? (v3 + 1.f) : expf(v3);
                }
            } else {
                v0 += bias[col]; v1 += bias[col + 1];
                v2 += bias[col]; v3 += bias[col + 1];
            }
            *(float2*)(dst + (size_t)row * nOut + col)       = make_float2(v0, v1);
            *(float2*)(dst + (size_t)(row + 8) * nOut + col) = make_float2(v2, v3);
        }
    }
}

// ---------------------------------------------------------------------------
// Chunk-local states: S_loc[b,h,c] = phi_k_chunk^T @ V_chunk, z_loc = colsum
// ---------------------------------------------------------------------------
__global__ __launch_bounds__(256)
void chunk_local_kernel(const float* __restrict__ pk, const float* __restrict__ vv,
                        float* __restrict__ Sloc, float* __restrict__ zloc)
{
    extern __shared__ float sm[];
    float* Pks = sm;                 // [C_][D_]
    float* Vs  = sm + C_ * D_;       // [C_][D_]

    const int c = blockIdx.x, h = blockIdx.y, b = blockIdx.z;
    const size_t base = ((size_t)b * L_ + (size_t)c * C_) * E_ + (size_t)h * D_;
    const float* pkb = pk + base;
    const float* vb  = vv + base;

    for (int i = threadIdx.x; i < C_ * D_ / 4; i += 256) {
        const int row = i >> 4;
        const int c4  = (i & 15) << 2;
        *(float4*)&Pks[row * D_ + c4] = *(const float4*)(pkb + (size_t)row * E_ + c4);
        *(float4*)&Vs [row * D_ + c4] = *(const float4*)(vb  + (size_t)row * E_ + c4);
    }
    __syncthreads();

    const int ty = threadIdx.x >> 4, tx = threadIdx.x & 15;
    float acc[4][4];
#pragma unroll
    for (int i = 0; i < 4; i++)
#pragma unroll
        for (int j = 0; j < 4; j++) acc[i][j] = 0.f;

#pragma unroll 4
    for (int t = 0; t < C_; t++) {
        float a[4], bb[4];
#pragma unroll
        for (int i = 0; i < 4; i++) a[i]  = Pks[t * D_ + ty * 4 + i];
#pragma unroll
        for (int j = 0; j < 4; j++) bb[j] = Vs [t * D_ + tx * 4 + j];
#pragma unroll
        for (int i = 0; i < 4; i++)
#pragma unroll
            for (int j = 0; j < 4; j++) acc[i][j] += a[i] * bb[j];
    }

    float* Sout = Sloc + ((((size_t)b * H_ + h) * NC_ + c) * D_ * D_);
#pragma unroll
    for (int i = 0; i < 4; i++)
#pragma unroll
        for (int j = 0; j < 4; j++)
            Sout[(ty * 4 + i) * D_ + tx * 4 + j] = acc[i][j];

    if (threadIdx.x < D_) {
        float s = 0.f;
#pragma unroll 8
        for (int t = 0; t < C_; t++) s += Pks[t * D_ + threadIdx.x];
        zloc[(((size_t)b * H_ + h) * NC_ + c) * D_ + threadIdx.x] = s;
    }
}

// ---------------------------------------------------------------------------
// Exclusive prefix over chunks, in place.
// ---------------------------------------------------------------------------
__global__ __launch_bounds__(256)
void prefix_kernel(float* __restrict__ S, float* __restrict__ z)
{
    const int bh = blockIdx.x;
    float* Sb = S + (size_t)bh * NC_ * D_ * D_;
    float* zb = z + (size_t)bh * NC_ * D_;

    for (int i = threadIdx.x; i < D_ * D_ / 4; i += 256) {
        float4 run = make_float4(0.f, 0.f, 0.f, 0.f);
        for (int c = 0; c < NC_; c++) {
            float4* p = (float4*)&Sb[(size_t)c * D_ * D_ + i * 4];
            float4 loc = *p;
            *p = run;
            run.x += loc.x; run.y += loc.y; run.z += loc.z; run.w += loc.w;
        }
    }
    for (int i = threadIdx.x; i < D_; i += 256) {
        float run = 0.f;
        for (int c = 0; c < NC_; c++) {
            const float loc = zb[(size_t)c * D_ + i];
            zb[(size_t)c * D_ + i] = run;
            run += loc;
        }
    }
}

// ---------------------------------------------------------------------------
// Chunk output -> writes attn as bf16 hi/lo for the tensor-core out-proj.
// ---------------------------------------------------------------------------
#define SM4_FLOATS (64*129 + 64*129 + 128*64 + 64*64 + 64 + 128*129 + 128)

__global__ __launch_bounds__(256)
void chunk_out_kernel(const float* __restrict__ pq, const float* __restrict__ pk,
                      const float* __restrict__ vv, const float* __restrict__ S,
                      const float* __restrict__ z,
                      __nv_bfloat16* __restrict__ attn_hi,
                      __nv_bfloat16* __restrict__ attn_lo)
{
    extern __shared__ float sm[];
    float* PqT = sm;                       // [D_][C_+1] k-major
    float* PkT = PqT + 64 * 129;           // [D_][C_+1]
    float* Vs  = PkT + 64 * 129;           // [C_][D_]
    float* Sp  = Vs + 128 * 64;            // [D_][D_]
    float* zp  = Sp + 64 * 64;             // [D_]
    float* Ms  = zp + 64;                  // [C_][C_+1]
    float* rs  = Ms + 128 * 129;           // [C_] 1/den

    const int c = blockIdx.x, h = blockIdx.y, b = blockIdx.z;
    const size_t base = ((size_t)b * L_ + (size_t)c * C_) * E_ + (size_t)h * D_;
    const float* pqb = pq + base;
    const float* pkb = pk + base;
    const float* vb  = vv + base;

    for (int i = threadIdx.x; i < C_ * D_ / 4; i += 256) {
        const int row = i >> 4;
        const int c4  = (i & 15) << 2;
        float4 qv = *(const float4*)(pqb + (size_t)row * E_ + c4);
        float4 kv = *(const float4*)(pkb + (size_t)row * E_ + c4);
        float4 wv = *(const float4*)(vb  + (size_t)row * E_ + c4);
        PqT[(c4 + 0) * 129 + row] = qv.x; PqT[(c4 + 1) * 129 + row] = qv.y;
        PqT[(c4 + 2) * 129 + row] = qv.z; PqT[(c4 + 3) * 129 + row] = qv.w;
        PkT[(c4 + 0) * 129 + row] = kv.x; PkT[(c4 + 1) * 129 + row] = kv.y;
        PkT[(c4 + 2) * 129 + row] = kv.z; PkT[(c4 + 3) * 129 + row] = kv.w;
        *(float4*)&Vs[row * D_ + c4] = wv;
    }
    {
        const float* Sb = S + (((size_t)b * H_ + h) * NC_ + c) * D_ * D_;
        for (int i = threadIdx.x; i < D_ * D_ / 4; i += 256)
            *(float4*)&Sp[i * 4] = *(const float4*)(Sb + (size_t)i * 4);
        if (threadIdx.x < D_ / 4) {
            const float* zbp = z + (((size_t)b * H_ + h) * NC_ + c) * D_;
            *(float4*)&zp[threadIdx.x * 4] = *(const float4*)(zbp + threadIdx.x * 4);
        }
    }
    __syncthreads();

    const int ty = threadIdx.x >> 4, tx = threadIdx.x & 15;

    // ---- phase 1: scores, causal mask -------------------------------------
    {
        float acc[8][8];
#pragma unroll
        for (int i = 0; i < 8; i++)
#pragma unroll
            for (int j = 0; j < 8; j++) acc[i][j] = 0.f;

#pragma unroll 4
        for (int k = 0; k < D_; k++) {
            float a[8], bb[8];
#pragma unroll
            for (int i = 0; i < 8; i++) a[i]  = PqT[k * 129 + ty * 8 + i];
#pragma unroll
            for (int j = 0; j < 8; j++) bb[j] = PkT[k * 129 + tx * 8 + j];
#pragma unroll
            for (int i = 0; i < 8; i++)
#pragma unroll
                for (int j = 0; j < 8; j++) acc[i][j] += a[i] * bb[j];
        }
#pragma unroll
        for (int i = 0; i < 8; i++) {
            const int t = ty * 8 + i;
#pragma unroll
            for (int j = 0; j < 8; j++) {
                const int s = tx * 8 + j;
                Ms[t * 129 + s] = (s <= t) ? acc[i][j] : 0.f;
            }
        }
    }
    __syncthreads();

    // ---- phase 2: denominators --------------------------------------------
    if (threadIdx.x < C_) {
        const int t = threadIdx.x;
        float ssum = 0.f;
#pragma unroll 8
        for (int j = 0; j < C_; j++) ssum += Ms[t * 129 + j];
        float dq = 0.f;
#pragma unroll 8
        for (int k = 0; k < D_; k++) dq += PqT[k * 129 + t] * zp[k];
        rs[t] = 1.f / (ssum + dq + EPS_);
    }
    __syncthreads();

    // ---- phase 3: outputs -------------------------------------------------
    {
        float acc[8][4];
#pragma unroll
        for (int i = 0; i < 8; i++)
#pragma unroll
            for (int j = 0; j < 4; j++) acc[i][j] = 0.f;

#pragma unroll 4
        for (int k = 0; k < D_; k++) {
            float a[8], bb[4];
#pragma unroll
            for (int i = 0; i < 8; i++) a[i]  = PqT[k * 129 + ty * 8 + i];
#pragma unroll
            for (int j = 0; j < 4; j++) bb[j] = Sp[k * D_ + tx * 4 + j];
#pragma unroll
            for (int i = 0; i < 8; i++)
#pragma unroll
                for (int j = 0; j < 4; j++) acc[i][j] += a[i] * bb[j];
        }
#pragma unroll 4
        for (int s = 0; s < C_; s++) {
            float a[8], bb[4];
#pragma unroll
            for (int i = 0; i < 8; i++) a[i]  = Ms[(ty * 8 + i) * 129 + s];
#pragma unroll
            for (int j = 0; j < 4; j++) bb[j] = Vs[s * D_ + tx * 4 + j];
#pragma unroll
            for (int i = 0; i < 8; i++)
#pragma unroll
                for (int j = 0; j < 4; j++) acc[i][j] += a[i] * bb[j];
        }

        __nv_bfloat16* obh = attn_hi + base;
        __nv_bfloat16* obl = attn_lo + base;
#pragma unroll
        for (int i = 0; i < 8; i++) {
            const float r = rs[ty * 8 + i];
            union { __nv_bfloat16 b[4]; uint2 u; } ph, pl;
#pragma unroll
            for (int j = 0; j < 4; j++) {
                float o = acc[i][j] * r;
                __nv_bfloat16 hbit = __float2bfloat16(o);
                ph.b[j] = hbit;
                pl.b[j] = __float2bfloat16(o - __bfloat162float(hbit));
            }
            const size_t off = (size_t)(ty * 8 + i) * E_ + tx * 4;
            *(uint2*)(obh + off) = ph.u;
            *(uint2*)(obl + off) = pl.u;
        }
    }
}

// ---------------------------------------------------------------------------
// Launch
// ---------------------------------------------------------------------------
extern "C" void kernel_launch(void* const* d_in, const int* in_sizes, int n_in,
                              void* d_out, int out_size)
{
    const float* x  = (const float*)d_in[0];
    const float* Wq = (const float*)d_in[1];
    const float* Wk = (const float*)d_in[2];
    const float* Wv = (const float*)d_in[3];
    const float* Wo = (const float*)d_in[4];
    const float* bo = (const float*)d_in[5];
    float* out = (float*)d_out;

    float *phi_q, *phi_k, *vbuf, *Sb, *zb;
    __nv_bfloat16 *xhi, *xlo, *ahi, *alo, *whi, *wlo;
    cudaGetSymbolAddress((void**)&phi_q, g_phi_q);
    cudaGetSymbolAddress((void**)&phi_k, g_phi_k);
    cudaGetSymbolAddress((void**)&vbuf,  g_v);
    cudaGetSymbolAddress((void**)&Sb,    g_S);
    cudaGetSymbolAddress((void**)&zb,    g_z);
    cudaGetSymbolAddress((void**)&xhi,   g_x_hi);
    cudaGetSymbolAddress((void**)&xlo,   g_x_lo);
    cudaGetSymbolAddress((void**)&ahi,   g_attn_hi);
    cudaGetSymbolAddress((void**)&alo,   g_attn_lo);
    cudaGetSymbolAddress((void**)&whi,   g_w_hi);
    cudaGetSymbolAddress((void**)&wlo,   g_w_lo);

    const int sm_local = 2 * C_ * D_ * (int)sizeof(float);
    const int sm_out   = SM4_FLOATS * (int)sizeof(float);
    (void)cudaFuncSetAttribute(chunk_local_kernel,
                               cudaFuncAttributeMaxDynamicSharedMemorySize, sm_local);
    (void)cudaFuncSetAttribute(chunk_out_kernel,
                               cudaFuncAttributeMaxDynamicSharedMemorySize, sm_out);
    (void)cudaFuncSetAttribute(gemm_bf16split<0>,
                               cudaFuncAttributeMaxDynamicSharedMemorySize, GEMM_SMEM);
    (void)cudaFuncSetAttribute(gemm_bf16split<1>,
                               cudaFuncAttributeMaxDynamicSharedMemorySize, GEMM_SMEM);

    // ---- split inputs to bf16 hi/lo ----
    const int nx4 = (MTOT * E_) / 4;
    split_kernel<<<(nx4 + 255) / 256, 256>>>(x, xhi, xlo, nx4);
    const int nw4 = (E_ * E_) / 4;
    const size_t wsz = (size_t)E_ * E_;
    split_kernel<<<(nw4 + 255) / 256, 256>>>(Wq, whi + 0 * wsz, wlo + 0 * wsz, nw4);
    split_kernel<<<(nw4 + 255) / 256, 256>>>(Wk, whi + 1 * wsz, wlo + 1 * wsz, nw4);
    split_kernel<<<(nw4 + 255) / 256, 256>>>(Wv, whi + 2 * wsz, wlo + 2 * wsz, nw4);
    split_kernel<<<(nw4 + 255) / 256, 256>>>(Wo, whi + 3 * wsz, wlo + 3 * wsz, nw4);

    // ---- fused QKV projection (tensor core): N = 3072 ----
    dim3 gqkv(3 * E_ / 128, MTOT / 128), gb(256);
    gemm_bf16split<1><<<gqkv, gb, GEMM_SMEM>>>(xhi, xlo, whi, wlo, nullptr,
                                               phi_q, phi_k, vbuf, MTOT, 3 * E_, E_);

    // ---- chunked linear attention ----
    dim3 gc(NC_, H_, B_);
    chunk_local_kernel<<<gc, 256, sm_local>>>(phi_k, vbuf, Sb, zb);
    prefix_kernel<<<B_ * H_, 256>>>(Sb, zb);
    chunk_out_kernel<<<gc, 256, sm_out>>>(phi_q, phi_k, vbuf, Sb, zb, ahi, alo);

    // ---- output projection + bias (tensor core) ----
    dim3 gout(E_ / 128, MTOT / 128);
    gemm_bf16split<0><<<gout, gb, GEMM_SMEM>>>(ahi, alo, whi + 3 * wsz, wlo + 3 * wsz,
                                               bo, out, nullptr, nullptr, MTOT, E_, E_);
}

// round 7
// speedup vs baseline: 2.6091x; 1.1040x over previous
#include <cuda_runtime.h>
#include <cuda_bf16.h>
#include <cstdint>
#include <cstddef>

// Problem constants
#define B_   4
#define L_   4096
#define E_   1024
#define H_   16
#define D_   64
#define C_   128          // chunk length
#define NC_  (L_ / C_)    // 32 chunks
#define MTOT (B_ * L_)    // 16384 rows
#define EPS_ 1e-5f

// ---------------------------------------------------------------------------
// Scratch (no cudaMalloc allowed -> __device__ globals)
// ---------------------------------------------------------------------------
__device__ float g_phi_q[(size_t)B_ * L_ * E_];
__device__ float g_phi_k[(size_t)B_ * L_ * E_];
__device__ float g_v    [(size_t)B_ * L_ * E_];
__device__ float g_S[(size_t)B_ * H_ * NC_ * D_ * D_];
__device__ float g_z[(size_t)B_ * H_ * NC_ * D_];

// bf16 split buffers
__device__ __nv_bfloat16 g_x_hi[(size_t)MTOT * E_];
__device__ __nv_bfloat16 g_x_lo[(size_t)MTOT * E_];
__device__ __nv_bfloat16 g_attn_hi[(size_t)MTOT * E_];
__device__ __nv_bfloat16 g_attn_lo[(size_t)MTOT * E_];
__device__ __nv_bfloat16 g_w_hi[4][(size_t)E_ * E_];   // q,k,v contiguous = [3072][1024]
__device__ __nv_bfloat16 g_w_lo[4][(size_t)E_ * E_];

// ---------------------------------------------------------------------------
// Common PTX helpers
// ---------------------------------------------------------------------------
__device__ __forceinline__ void mma_bf16(float* c, const uint32_t* a, const uint32_t* b)
{
    asm volatile(
        "mma.sync.aligned.m16n8k16.row.col.f32.bf16.bf16.f32 "
        "{%0,%1,%2,%3}, {%4,%5,%6,%7}, {%8,%9}, {%0,%1,%2,%3};\n"
        : "+f"(c[0]), "+f"(c[1]), "+f"(c[2]), "+f"(c[3])
        : "r"(a[0]), "r"(a[1]), "r"(a[2]), "r"(a[3]), "r"(b[0]), "r"(b[1]));
}

__device__ __forceinline__ void ldm_x4(uint32_t* r, uint32_t addr)
{
    asm volatile("ldmatrix.sync.aligned.m8n8.x4.shared.b16 {%0,%1,%2,%3}, [%4];\n"
                 : "=r"(r[0]), "=r"(r[1]), "=r"(r[2]), "=r"(r[3]) : "r"(addr));
}

__device__ __forceinline__ void ldm_x4t(uint32_t* r, uint32_t addr)
{
    asm volatile("ldmatrix.sync.aligned.m8n8.x4.trans.shared.b16 {%0,%1,%2,%3}, [%4];\n"
                 : "=r"(r[0]), "=r"(r[1]), "=r"(r[2]), "=r"(r[3]) : "r"(addr));
}

__device__ __forceinline__ uint32_t packbf(float a, float b)
{
    __nv_bfloat162 h = __floats2bfloat162_rn(a, b);
    return *(uint32_t*)&h;
}

__device__ __forceinline__ void cp16(__nv_bfloat16* dst, const __nv_bfloat16* src)
{
    uint32_t d = (uint32_t)__cvta_generic_to_shared(dst);
    asm volatile("cp.async.cg.shared.global [%0], [%1], 16;\n" :: "r"(d), "l"(src));
}
__device__ __forceinline__ void cp_commit() { asm volatile("cp.async.commit_group;\n"); }
__device__ __forceinline__ void cp_wait1()  { asm volatile("cp.async.wait_group 1;\n"); }
__device__ __forceinline__ void cp_wait0()  { asm volatile("cp.async.wait_group 0;\n"); }

// ---------------------------------------------------------------------------
// Split fp32 -> bf16 hi + bf16 lo
// ---------------------------------------------------------------------------
__global__ __launch_bounds__(256)
void split_kernel(const float* __restrict__ in, __nv_bfloat16* __restrict__ hi,
                  __nv_bfloat16* __restrict__ lo, int n4)
{
    int i = blockIdx.x * 256 + threadIdx.x;
    if (i >= n4) return;
    float4 v = ((const float4*)in)[i];
    __nv_bfloat16 h0 = __float2bfloat16(v.x);
    __nv_bfloat16 h1 = __float2bfloat16(v.y);
    __nv_bfloat16 h2 = __float2bfloat16(v.z);
    __nv_bfloat16 h3 = __float2bfloat16(v.w);
    __nv_bfloat16 l0 = __float2bfloat16(v.x - __bfloat162float(h0));
    __nv_bfloat16 l1 = __float2bfloat16(v.y - __bfloat162float(h1));
    __nv_bfloat16 l2 = __float2bfloat16(v.z - __bfloat162float(h2));
    __nv_bfloat16 l3 = __float2bfloat16(v.w - __bfloat162float(h3));
    union { __nv_bfloat16 b[4]; uint2 u; } ph, pl;
    ph.b[0] = h0; ph.b[1] = h1; ph.b[2] = h2; ph.b[3] = h3;
    pl.b[0] = l0; pl.b[1] = l1; pl.b[2] = l2; pl.b[3] = l3;
    ((uint2*)hi)[i] = ph.u;
    ((uint2*)lo)[i] = pl.u;
}

// ---------------------------------------------------------------------------
// Tensor-core GEMM, bf16 2-term split (hi*hi + hi*lo + lo*hi), ldmatrix loads.
// MODE 0: single output + bias.  MODE 1: fused QKV (N=3072), elu+1 on q,k.
// ---------------------------------------------------------------------------
#define SROW 40
#define STAGE_ELEMS (4 * 128 * SROW)
#define GEMM_SMEM (2 * STAGE_ELEMS * 2)

template <int MODE>
__global__ __launch_bounds__(256, 2)
void gemm_bf16split(const __nv_bfloat16* __restrict__ Ahi, const __nv_bfloat16* __restrict__ Alo,
                    const __nv_bfloat16* __restrict__ Bhi, const __nv_bfloat16* __restrict__ Blo,
                    const float* __restrict__ bias,
                    float* __restrict__ out0, float* __restrict__ out1, float* __restrict__ out2,
                    int M, int N, int K)
{
    extern __shared__ __nv_bfloat16 smem[];

    const int tid  = threadIdx.x;
    const int bm   = blockIdx.y * 128;
    const int bn   = blockIdx.x * 128;
    const int warp = tid >> 5, lane = tid & 31;
    const int wm   = (warp & 3) * 32;
    const int wn   = (warp >> 2) * 64;
    const int gid  = lane >> 2;
    const int tig  = lane & 3;

    const int KT = K / 32;

    __nv_bfloat16* stage0 = smem;
    __nv_bfloat16* stage1 = smem + STAGE_ELEMS;
    const uint32_t st0s = (uint32_t)__cvta_generic_to_shared(stage0);
    const uint32_t st1s = st0s + STAGE_ELEMS * 2;
    const uint32_t ALO_OFF = 128 * SROW * 2;
    const uint32_t BHI_OFF = 2 * 128 * SROW * 2;
    const uint32_t BLO_OFF = 3 * 128 * SROW * 2;

    const int lidx = lane & 7;
    const int lmat = lane >> 3;
    int aoff[2];
#pragma unroll
    for (int mi = 0; mi < 2; mi++)
        aoff[mi] = (wm + mi * 16 + ((lmat & 1) << 3) + lidx) * SROW + ((lmat >> 1) << 3);
    int boff[4];
#pragma unroll
    for (int p = 0; p < 4; p++)
        boff[p] = (wn + p * 16 + ((lmat >> 1) << 3) + lidx) * SROW + ((lmat & 1) << 3);

    auto issue = [&](int kt, int s) {
        __nv_bfloat16* sAh = s ? stage1 : stage0;
        __nv_bfloat16* sAl = sAh + 128 * SROW;
        __nv_bfloat16* sBh = sAl + 128 * SROW;
        __nv_bfloat16* sBl = sBh + 128 * SROW;
        const int kbase = kt * 32;
#pragma unroll
        for (int c = 0; c < 2; c++) {
            int q   = tid + c * 256;
            int row = q >> 2;
            int kc  = (q & 3) << 3;
            const size_t ga = (size_t)(bm + row) * K + kbase + kc;
            const size_t gb = (size_t)(bn + row) * K + kbase + kc;
            cp16(sAh + row * SROW + kc, Ahi + ga);
            cp16(sAl + row * SROW + kc, Alo + ga);
            cp16(sBh + row * SROW + kc, Bhi + gb);
            cp16(sBl + row * SROW + kc, Blo + gb);
        }
        cp_commit();
    };

    float acc[2][8][4];
#pragma unroll
    for (int mi = 0; mi < 2; mi++)
#pragma unroll
        for (int ni = 0; ni < 8; ni++)
#pragma unroll
            for (int j = 0; j < 4; j++) acc[mi][ni][j] = 0.f;

    issue(0, 0);
    issue(1, 1);

    for (int kt = 0; kt < KT; kt++) {
        if (kt + 1 < KT) cp_wait1(); else cp_wait0();
        __syncthreads();

        const uint32_t sb = (kt & 1) ? st1s : st0s;

#pragma unroll
        for (int ks = 0; ks < 2; ks++) {
            const uint32_t kofs = (uint32_t)(ks * 16) * 2;
            uint32_t ahi[2][4], alo[2][4];
#pragma unroll
            for (int mi = 0; mi < 2; mi++) {
                const uint32_t ab = sb + (uint32_t)aoff[mi] * 2 + kofs;
                ldm_x4(ahi[mi], ab);
                ldm_x4(alo[mi], ab + ALO_OFF);
            }
#pragma unroll
            for (int p = 0; p < 4; p++) {
                uint32_t bh4[4], bl4[4];
                const uint32_t bb = sb + BHI_OFF + (uint32_t)boff[p] * 2 + kofs;
                ldm_x4(bh4, bb);
                ldm_x4(bl4, bb + (BLO_OFF - BHI_OFF));
#pragma unroll
                for (int sub = 0; sub < 2; sub++) {
                    const uint32_t bh2[2] = { bh4[sub * 2], bh4[sub * 2 + 1] };
                    const uint32_t bl2[2] = { bl4[sub * 2], bl4[sub * 2 + 1] };
                    const int ni = p * 2 + sub;
#pragma unroll
                    for (int mi = 0; mi < 2; mi++) {
                        mma_bf16(acc[mi][ni], ahi[mi], bh2);
                        mma_bf16(acc[mi][ni], ahi[mi], bl2);
                        mma_bf16(acc[mi][ni], alo[mi], bh2);
                    }
                }
            }
        }
        __syncthreads();
        if (kt + 2 < KT) issue(kt + 2, kt & 1);
    }

    float* dst;
    int col_base, nOut;
    bool do_elu = false;
    if (MODE == 1) {
        const int seg = (int)blockIdx.x >> 3;
        dst = (seg == 0) ? out0 : (seg == 1) ? out1 : out2;
        col_base = ((int)blockIdx.x & 7) * 128;
        nOut = 1024;
        do_elu = (seg < 2);
    } else {
        dst = out0; col_base = bn; nOut = N;
    }

#pragma unroll
    for (int mi = 0; mi < 2; mi++) {
#pragma unroll
        for (int ni = 0; ni < 8; ni++) {
            const int row = bm + wm + mi * 16 + gid;
            const int col = col_base + wn + ni * 8 + tig * 2;
            float v0 = acc[mi][ni][0], v1 = acc[mi][ni][1];
            float v2 = acc[mi][ni][2], v3 = acc[mi][ni][3];
            if (MODE == 1) {
                if (do_elu) {
                    v0 = (v0 > 0.f) ? (v0 + 1.f) : expf(v0);
                    v1 = (v1 > 0.f) ? (v1 + 1.f) : expf(v1);
                    v2 = (v2 > 0.f) ? (v2 + 1.f) : expf(v2);
                    v3 = (v3 > 0.f) ? (v3 + 1.f) : expf(v3);
                }
            } else {
                v0 += bias[col]; v1 += bias[col + 1];
                v2 += bias[col]; v3 += bias[col + 1];
            }
            *(float2*)(dst + (size_t)row * nOut + col)       = make_float2(v0, v1);
            *(float2*)(dst + (size_t)(row + 8) * nOut + col) = make_float2(v2, v3);
        }
    }
}

// ---------------------------------------------------------------------------
// Chunk-local states: S_loc[b,h,c] = phi_k_chunk^T @ V_chunk, z_loc = colsum
// ---------------------------------------------------------------------------
__global__ __launch_bounds__(256)
void chunk_local_kernel(const float* __restrict__ pk, const float* __restrict__ vv,
                        float* __restrict__ Sloc, float* __restrict__ zloc)
{
    extern __shared__ float sm[];
    float* Pks = sm;                 // [C_][D_]
    float* Vs  = sm + C_ * D_;       // [C_][D_]

    const int c = blockIdx.x, h = blockIdx.y, b = blockIdx.z;
    const size_t base = ((size_t)b * L_ + (size_t)c * C_) * E_ + (size_t)h * D_;
    const float* pkb = pk + base;
    const float* vb  = vv + base;

    for (int i = threadIdx.x; i < C_ * D_ / 4; i += 256) {
        const int row = i >> 4;
        const int c4  = (i & 15) << 2;
        *(float4*)&Pks[row * D_ + c4] = *(const float4*)(pkb + (size_t)row * E_ + c4);
        *(float4*)&Vs [row * D_ + c4] = *(const float4*)(vb  + (size_t)row * E_ + c4);
    }
    __syncthreads();

    const int ty = threadIdx.x >> 4, tx = threadIdx.x & 15;
    float acc[4][4];
#pragma unroll
    for (int i = 0; i < 4; i++)
#pragma unroll
        for (int j = 0; j < 4; j++) acc[i][j] = 0.f;

#pragma unroll 4
    for (int t = 0; t < C_; t++) {
        float a[4], bb[4];
#pragma unroll
        for (int i = 0; i < 4; i++) a[i]  = Pks[t * D_ + ty * 4 + i];
#pragma unroll
        for (int j = 0; j < 4; j++) bb[j] = Vs [t * D_ + tx * 4 + j];
#pragma unroll
        for (int i = 0; i < 4; i++)
#pragma unroll
            for (int j = 0; j < 4; j++) acc[i][j] += a[i] * bb[j];
    }

    float* Sout = Sloc + ((((size_t)b * H_ + h) * NC_ + c) * D_ * D_);
#pragma unroll
    for (int i = 0; i < 4; i++)
#pragma unroll
        for (int j = 0; j < 4; j++)
            Sout[(ty * 4 + i) * D_ + tx * 4 + j] = acc[i][j];

    if (threadIdx.x < D_) {
        float s = 0.f;
#pragma unroll 8
        for (int t = 0; t < C_; t++) s += Pks[t * D_ + threadIdx.x];
        zloc[(((size_t)b * H_ + h) * NC_ + c) * D_ + threadIdx.x] = s;
    }
}

// ---------------------------------------------------------------------------
// Exclusive prefix over chunks, in place.
// ---------------------------------------------------------------------------
__global__ __launch_bounds__(256)
void prefix_kernel(float* __restrict__ S, float* __restrict__ z)
{
    const int bh = blockIdx.x;
    float* Sb = S + (size_t)bh * NC_ * D_ * D_;
    float* zb = z + (size_t)bh * NC_ * D_;

    for (int i = threadIdx.x; i < D_ * D_ / 4; i += 256) {
        float4 run = make_float4(0.f, 0.f, 0.f, 0.f);
        for (int c = 0; c < NC_; c++) {
            float4* p = (float4*)&Sb[(size_t)c * D_ * D_ + i * 4];
            float4 loc = *p;
            *p = run;
            run.x += loc.x; run.y += loc.y; run.z += loc.z; run.w += loc.w;
        }
    }
    for (int i = threadIdx.x; i < D_; i += 256) {
        float run = 0.f;
        for (int c = 0; c < NC_; c++) {
            const float loc = zb[(size_t)c * D_ + i];
            zb[(size_t)c * D_ + i] = run;
            run += loc;
        }
    }
}

// ---------------------------------------------------------------------------
// Chunk output (tensor-core): per block one (b,h,chunk).
//   M = causal(phi_q @ phi_k^T); den = phi_q.z + rowsum(M) + eps
//   O = (phi_q @ S + M @ V) / den    -> attn hi/lo bf16
// 8 warps; warp w owns rows 16w..16w+15. All matmuls: bf16 hi/lo 3-term mma.
// ---------------------------------------------------------------------------
#define QROW 72
#define OFF_QHI 0
#define OFF_QLO (OFF_QHI + 128 * QROW)
#define OFF_KHI (OFF_QLO + 128 * QROW)
#define OFF_KLO (OFF_KHI + 128 * QROW)
#define OFF_VHI (OFF_KLO + 128 * QROW)
#define OFF_VLO (OFF_VHI + 128 * QROW)
#define OFF_STHI (OFF_VLO + 128 * QROW)
#define OFF_STLO (OFF_STHI + 64 * QROW)
#define OFF_Z    (OFF_STLO + 64 * QROW)   // 64 floats = 128 bf16 slots
#define CO_SMEM ((OFF_Z + 128) * 2)

__global__ __launch_bounds__(256)
void chunk_out_kernel(const float* __restrict__ pq, const float* __restrict__ pk,
                      const float* __restrict__ vv, const float* __restrict__ S,
                      const float* __restrict__ z,
                      __nv_bfloat16* __restrict__ attn_hi,
                      __nv_bfloat16* __restrict__ attn_lo)
{
    extern __shared__ __nv_bfloat16 cs[];
    const uint32_t sbase = (uint32_t)__cvta_generic_to_shared(cs);

    const int tid  = threadIdx.x;
    const int warp = tid >> 5, lane = tid & 31;
    const int g    = lane >> 2, t = lane & 3;
    const int lidx = lane & 7,  lmat = lane >> 3;

    const int c = blockIdx.x, h = blockIdx.y, b = blockIdx.z;
    const size_t base = ((size_t)b * L_ + (size_t)c * C_) * E_ + (size_t)h * D_;
    const float* pqb = pq + base;
    const float* pkb = pk + base;
    const float* vb  = vv + base;

    // ---- load fp32, split to bf16 hi/lo in smem ---------------------------
    for (int i = tid; i < 128 * 16; i += 256) {
        const int row = i >> 4;
        const int c4  = (i & 15) << 2;
        float4 qv = *(const float4*)(pqb + (size_t)row * E_ + c4);
        float4 kv = *(const float4*)(pkb + (size_t)row * E_ + c4);
        float4 wv = *(const float4*)(vb  + (size_t)row * E_ + c4);
        const float* vals[3] = { (float*)&qv, (float*)&kv, (float*)&wv };
        const int offs_hi[3] = { OFF_QHI, OFF_KHI, OFF_VHI };
        const int offs_lo[3] = { OFF_QLO, OFF_KLO, OFF_VLO };
#pragma unroll
        for (int p = 0; p < 3; p++) {
            union { __nv_bfloat16 bx[4]; uint2 u; } ph, pl;
#pragma unroll
            for (int j = 0; j < 4; j++) {
                float v = vals[p][j];
                __nv_bfloat16 hb = __float2bfloat16(v);
                ph.bx[j] = hb;
                pl.bx[j] = __float2bfloat16(v - __bfloat162float(hb));
            }
            *(uint2*)&cs[offs_hi[p] + row * QROW + c4] = ph.u;
            *(uint2*)&cs[offs_lo[p] + row * QROW + c4] = pl.u;
        }
    }
    // S (64x64) -> transposed hi/lo (ST[n][k] = S[k][n]); z -> fp32 smem
    {
        const float* Sb = S + (((size_t)b * H_ + h) * NC_ + c) * D_ * D_;
        for (int i = tid; i < 64 * 16; i += 256) {
            const int r  = i >> 4;
            const int c4 = (i & 15) << 2;
            float4 sv = *(const float4*)(Sb + (size_t)r * D_ + c4);
            const float* sp = (const float*)&sv;
#pragma unroll
            for (int j = 0; j < 4; j++) {
                const int col = c4 + j;
                float v = sp[j];
                __nv_bfloat16 hb = __float2bfloat16(v);
                cs[OFF_STHI + col * QROW + r] = hb;
                cs[OFF_STLO + col * QROW + r] = __float2bfloat16(v - __bfloat162float(hb));
            }
        }
        if (tid < 64) {
            const float* zbp = z + (((size_t)b * H_ + h) * NC_ + c) * D_;
            ((float*)(cs + OFF_Z))[tid] = zbp[tid];
        }
    }
    __syncthreads();

    // common ldmatrix offsets (bytes, within a plane)
    const uint32_t aoff_b =
        (uint32_t)(((16 * warp + ((lmat & 1) << 3) + lidx) * QROW + ((lmat >> 1) << 3)) * 2);

    // ---- phase 1: M = phi_q @ phi_k^T (rows 16w..16w+15 x cols 0..127) ----
    float mC[16][4];
#pragma unroll
    for (int j = 0; j < 16; j++)
#pragma unroll
        for (int q = 0; q < 4; q++) mC[j][q] = 0.f;

#pragma unroll
    for (int ks = 0; ks < 4; ks++) {
        uint32_t aqh[4], aql[4];
        const uint32_t qa = sbase + OFF_QHI * 2 + aoff_b + ks * 32;
        ldm_x4(aqh, qa);
        ldm_x4(aql, qa + (OFF_QLO - OFF_QHI) * 2);
#pragma unroll
        for (int p = 0; p < 8; p++) {
            const uint32_t bb = sbase + OFF_KHI * 2 +
                (uint32_t)(((p * 16 + ((lmat >> 1) << 3) + lidx) * QROW + ((lmat & 1) << 3)) * 2)
                + ks * 32;
            uint32_t bh4[4], bl4[4];
            ldm_x4(bh4, bb);
            ldm_x4(bl4, bb + (OFF_KLO - OFF_KHI) * 2);
#pragma unroll
            for (int sub = 0; sub < 2; sub++) {
                const uint32_t bh2[2] = { bh4[sub * 2], bh4[sub * 2 + 1] };
                const uint32_t bl2[2] = { bl4[sub * 2], bl4[sub * 2 + 1] };
                mma_bf16(mC[2 * p + sub], aqh, bh2);
                mma_bf16(mC[2 * p + sub], aqh, bl2);
                mma_bf16(mC[2 * p + sub], aql, bh2);
            }
        }
    }

    // ---- mask, rowsums, repack M into A fragments (hi/lo) -----------------
    const int row0 = 16 * warp + g;
    const int row1 = row0 + 8;
    float pg = 0.f, pg8 = 0.f;
#pragma unroll
    for (int j = 0; j < 16; j++) {
        const int c0 = 8 * j + 2 * t;
        if (c0 > row0)     mC[j][0] = 0.f;
        if (c0 + 1 > row0) mC[j][1] = 0.f;
        if (c0 > row1)     mC[j][2] = 0.f;
        if (c0 + 1 > row1) mC[j][3] = 0.f;
        pg  += mC[j][0] + mC[j][1];
        pg8 += mC[j][2] + mC[j][3];
    }

    uint32_t mh[8][4], ml[8][4];
#pragma unroll
    for (int ks = 0; ks < 8; ks++) {
#pragma unroll
        for (int q = 0; q < 4; q++) {
            const int j = 2 * ks + (q >> 1);
            const int lohalf = (q & 1) * 2;
            float v0 = mC[j][lohalf], v1 = mC[j][lohalf + 1];
            float h0 = __bfloat162float(__float2bfloat16(v0));
            float h1 = __bfloat162float(__float2bfloat16(v1));
            mh[ks][q] = packbf(h0, h1);
            ml[ks][q] = packbf(v0 - h0, v1 - h1);
        }
    }
    // NOTE on q-ordering: A frag = {a0:(g,k0+2t),a1:(g+8,k0+2t),a2:(g,k0+8+2t),a3:(g+8,k0+8+2t)}
    //  a0 <- tile 2ks regs {0,1} (row g);  a1 <- tile 2ks regs {2,3} (row g+8)
    //  a2 <- tile 2ks+1 regs {0,1};        a3 <- tile 2ks+1 regs {2,3}
    //  mapping above: q=0 -> j=2ks,lohalf0 (row g)    = a0  OK
    //                 q=1 -> j=2ks,lohalf2 (row g+8)  = a1  OK
    //                 q=2 -> j=2ks+1,half0 (row g)    = a2  OK
    //                 q=3 -> j=2ks+1,half2 (row g+8)  = a3  OK

    // rowsum reduce across the quad (lanes sharing g)
    pg  += __shfl_xor_sync(0xffffffffu, pg, 1);
    pg  += __shfl_xor_sync(0xffffffffu, pg, 2);
    pg8 += __shfl_xor_sync(0xffffffffu, pg8, 1);
    pg8 += __shfl_xor_sync(0xffffffffu, pg8, 2);

    // dq = phi_q[row] . z  (lanes 0..15 compute one row each)
    float dqv = 0.f;
    if (lane < 16) {
        const int r = 16 * warp + lane;
        const float* zf = (const float*)(cs + OFF_Z);
#pragma unroll 8
        for (int k = 0; k < 64; k++) {
            float qv = __bfloat162float(cs[OFF_QHI + r * QROW + k]) +
                       __bfloat162float(cs[OFF_QLO + r * QROW + k]);
            dqv += qv * zf[k];
        }
    }
    const float dq0 = __shfl_sync(0xffffffffu, dqv, g);
    const float dq8 = __shfl_sync(0xffffffffu, dqv, g + 8);
    const float rs0 = 1.f / (pg  + dq0 + EPS_);
    const float rs1 = 1.f / (pg8 + dq8 + EPS_);

    // ---- phase 3: O = phi_q @ S + M @ V -----------------------------------
    float acc[8][4];
#pragma unroll
    for (int nt = 0; nt < 8; nt++)
#pragma unroll
        for (int q = 0; q < 4; q++) acc[nt][q] = 0.f;

    // 3a: phi_q @ S  (B = ST planes, n=64)
#pragma unroll
    for (int ks = 0; ks < 4; ks++) {
        uint32_t aqh[4], aql[4];
        const uint32_t qa = sbase + OFF_QHI * 2 + aoff_b + ks * 32;
        ldm_x4(aqh, qa);
        ldm_x4(aql, qa + (OFF_QLO - OFF_QHI) * 2);
#pragma unroll
        for (int p = 0; p < 4; p++) {
            const uint32_t bb = sbase + OFF_STHI * 2 +
                (uint32_t)(((p * 16 + ((lmat >> 1) << 3) + lidx) * QROW + ((lmat & 1) << 3)) * 2)
                + ks * 32;
            uint32_t bh4[4], bl4[4];
            ldm_x4(bh4, bb);
            ldm_x4(bl4, bb + (OFF_STLO - OFF_STHI) * 2);
#pragma unroll
            for (int sub = 0; sub < 2; sub++) {
                const uint32_t bh2[2] = { bh4[sub * 2], bh4[sub * 2 + 1] };
                const uint32_t bl2[2] = { bl4[sub * 2], bl4[sub * 2 + 1] };
                mma_bf16(acc[2 * p + sub], aqh, bh2);
                mma_bf16(acc[2 * p + sub], aqh, bl2);
                mma_bf16(acc[2 * p + sub], aql, bh2);
            }
        }
    }

    // 3b: M @ V  (B via ldmatrix.trans on V[s][d]; one x4 = 2 ksteps)
#pragma unroll
    for (int kb = 0; kb < 4; kb++) {
        const int k0e = kb * 32;
        const int ks  = kb * 2;
#pragma unroll
        for (int nt = 0; nt < 8; nt++) {
            const uint32_t va = sbase + OFF_VHI * 2 +
                (uint32_t)(((k0e + lmat * 8 + lidx) * QROW) * 2) + nt * 16;
            uint32_t vh[4], vl[4];
            ldm_x4t(vh, va);
            ldm_x4t(vl, va + (OFF_VLO - OFF_VHI) * 2);
#pragma unroll
            for (int sub = 0; sub < 2; sub++) {
                const uint32_t bh2[2] = { vh[sub * 2], vh[sub * 2 + 1] };
                const uint32_t bl2[2] = { vl[sub * 2], vl[sub * 2 + 1] };
                mma_bf16(acc[nt], mh[ks + sub], bh2);
                mma_bf16(acc[nt], mh[ks + sub], bl2);
                mma_bf16(acc[nt], ml[ks + sub], bh2);
            }
        }
    }

    // ---- epilogue: scale by 1/den, write attn hi/lo -----------------------
    __nv_bfloat16* obh = attn_hi + base;
    __nv_bfloat16* obl = attn_lo + base;
#pragma unroll
    for (int nt = 0; nt < 8; nt++) {
        const int col = 8 * nt + 2 * t;
        float v0 = acc[nt][0] * rs0, v1 = acc[nt][1] * rs0;
        float v2 = acc[nt][2] * rs1, v3 = acc[nt][3] * rs1;
        float h0 = __bfloat162float(__float2bfloat16(v0));
        float h1 = __bfloat162float(__float2bfloat16(v1));
        float h2 = __bfloat162float(__float2bfloat16(v2));
        float h3 = __bfloat162float(__float2bfloat16(v3));
        *(uint32_t*)(obh + (size_t)row0 * E_ + col) = packbf(h0, h1);
        *(uint32_t*)(obl + (size_t)row0 * E_ + col) = packbf(v0 - h0, v1 - h1);
        *(uint32_t*)(obh + (size_t)row1 * E_ + col) = packbf(h2, h3);
        *(uint32_t*)(obl + (size_t)row1 * E_ + col) = packbf(v2 - h2, v3 - h3);
    }
}

// ---------------------------------------------------------------------------
// Launch
// ---------------------------------------------------------------------------
extern "C" void kernel_launch(void* const* d_in, const int* in_sizes, int n_in,
                              void* d_out, int out_size)
{
    const float* x  = (const float*)d_in[0];
    const float* Wq = (const float*)d_in[1];
    const float* Wk = (const float*)d_in[2];
    const float* Wv = (const float*)d_in[3];
    const float* Wo = (const float*)d_in[4];
    const float* bo = (const float*)d_in[5];
    float* out = (float*)d_out;

    float *phi_q, *phi_k, *vbuf, *Sb, *zb;
    __nv_bfloat16 *xhi, *xlo, *ahi, *alo, *whi, *wlo;
    cudaGetSymbolAddress((void**)&phi_q, g_phi_q);
    cudaGetSymbolAddress((void**)&phi_k, g_phi_k);
    cudaGetSymbolAddress((void**)&vbuf,  g_v);
    cudaGetSymbolAddress((void**)&Sb,    g_S);
    cudaGetSymbolAddress((void**)&zb,    g_z);
    cudaGetSymbolAddress((void**)&xhi,   g_x_hi);
    cudaGetSymbolAddress((void**)&xlo,   g_x_lo);
    cudaGetSymbolAddress((void**)&ahi,   g_attn_hi);
    cudaGetSymbolAddress((void**)&alo,   g_attn_lo);
    cudaGetSymbolAddress((void**)&whi,   g_w_hi);
    cudaGetSymbolAddress((void**)&wlo,   g_w_lo);

    const int sm_local = 2 * C_ * D_ * (int)sizeof(float);
    (void)cudaFuncSetAttribute(chunk_local_kernel,
                               cudaFuncAttributeMaxDynamicSharedMemorySize, sm_local);
    (void)cudaFuncSetAttribute(chunk_out_kernel,
                               cudaFuncAttributeMaxDynamicSharedMemorySize, CO_SMEM);
    (void)cudaFuncSetAttribute(gemm_bf16split<0>,
                               cudaFuncAttributeMaxDynamicSharedMemorySize, GEMM_SMEM);
    (void)cudaFuncSetAttribute(gemm_bf16split<1>,
                               cudaFuncAttributeMaxDynamicSharedMemorySize, GEMM_SMEM);

    // ---- split inputs to bf16 hi/lo ----
    const int nx4 = (MTOT * E_) / 4;
    split_kernel<<<(nx4 + 255) / 256, 256>>>(x, xhi, xlo, nx4);
    const int nw4 = (E_ * E_) / 4;
    const size_t wsz = (size_t)E_ * E_;
    split_kernel<<<(nw4 + 255) / 256, 256>>>(Wq, whi + 0 * wsz, wlo + 0 * wsz, nw4);
    split_kernel<<<(nw4 + 255) / 256, 256>>>(Wk, whi + 1 * wsz, wlo + 1 * wsz, nw4);
    split_kernel<<<(nw4 + 255) / 256, 256>>>(Wv, whi + 2 * wsz, wlo + 2 * wsz, nw4);
    split_kernel<<<(nw4 + 255) / 256, 256>>>(Wo, whi + 3 * wsz, wlo + 3 * wsz, nw4);

    // ---- fused QKV projection (tensor core): N = 3072 ----
    dim3 gqkv(3 * E_ / 128, MTOT / 128), gb(256);
    gemm_bf16split<1><<<gqkv, gb, GEMM_SMEM>>>(xhi, xlo, whi, wlo, nullptr,
                                               phi_q, phi_k, vbuf, MTOT, 3 * E_, E_);

    // ---- chunked linear attention ----
    dim3 gc(NC_, H_, B_);
    chunk_local_kernel<<<gc, 256, sm_local>>>(phi_k, vbuf, Sb, zb);
    prefix_kernel<<<B_ * H_, 256>>>(Sb, zb);
    chunk_out_kernel<<<gc, 256, CO_SMEM>>>(phi_q, phi_k, vbuf, Sb, zb, ahi, alo);

    // ---- output projection + bias (tensor core) ----
    dim3 gout(E_ / 128, MTOT / 128);
    gemm_bf16split<0><<<gout, gb, GEMM_SMEM>>>(ahi, alo, whi + 3 * wsz, wlo + 3 * wsz,
                                               bo, out, nullptr, nullptr, MTOT, E_, E_);
}

// round 10
// speedup vs baseline: 3.3792x; 1.2952x over previous
#include <cuda_runtime.h>
#include <cuda_fp16.h>
#include <cuda_bf16.h>
#include <cstdint>
#include <cstddef>

// Problem constants
#define B_   4
#define L_   4096
#define E_   1024
#define H_   16
#define D_   64
#define C_   128
#define NC_  (L_ / C_)
#define MTOT (B_ * L_)
#define EPS_ 1e-5f

// ---------------------------------------------------------------------------
// Scratch
// ---------------------------------------------------------------------------
__device__ float g_phi_q[(size_t)B_ * L_ * E_];
__device__ float g_phi_k[(size_t)B_ * L_ * E_];
__device__ float g_v    [(size_t)B_ * L_ * E_];
__device__ float g_S[(size_t)B_ * H_ * NC_ * D_ * D_];
__device__ float g_z[(size_t)B_ * H_ * NC_ * D_];

// fp16 split buffers (only the A-side residual is consumed by the GEMMs)
__device__ __half g_x_hi[(size_t)MTOT * E_];
__device__ __half g_x_lo[(size_t)MTOT * E_];
__device__ __half g_attn_hi[(size_t)MTOT * E_];
__device__ __half g_attn_lo[(size_t)MTOT * E_];
__device__ __half g_w_hi[4][(size_t)E_ * E_];   // q,k,v contiguous = [3072][1024]

// ---------------------------------------------------------------------------
// PTX helpers
// ---------------------------------------------------------------------------
__device__ __forceinline__ void mma_f16(float* c, const uint32_t* a, const uint32_t* b)
{
    asm volatile(
        "mma.sync.aligned.m16n8k16.row.col.f32.f16.f16.f32 "
        "{%0,%1,%2,%3}, {%4,%5,%6,%7}, {%8,%9}, {%0,%1,%2,%3};\n"
        : "+f"(c[0]), "+f"(c[1]), "+f"(c[2]), "+f"(c[3])
        : "r"(a[0]), "r"(a[1]), "r"(a[2]), "r"(a[3]), "r"(b[0]), "r"(b[1]));
}
__device__ __forceinline__ void mma_bf16(float* c, const uint32_t* a, const uint32_t* b)
{
    asm volatile(
        "mma.sync.aligned.m16n8k16.row.col.f32.bf16.bf16.f32 "
        "{%0,%1,%2,%3}, {%4,%5,%6,%7}, {%8,%9}, {%0,%1,%2,%3};\n"
        : "+f"(c[0]), "+f"(c[1]), "+f"(c[2]), "+f"(c[3])
        : "r"(a[0]), "r"(a[1]), "r"(a[2]), "r"(a[3]), "r"(b[0]), "r"(b[1]));
}

__device__ __forceinline__ void ldm_x4(uint32_t* r, uint32_t addr)
{
    asm volatile("ldmatrix.sync.aligned.m8n8.x4.shared.b16 {%0,%1,%2,%3}, [%4];\n"
                 : "=r"(r[0]), "=r"(r[1]), "=r"(r[2]), "=r"(r[3]) : "r"(addr));
}
__device__ __forceinline__ void ldm_x4t(uint32_t* r, uint32_t addr)
{
    asm volatile("ldmatrix.sync.aligned.m8n8.x4.trans.shared.b16 {%0,%1,%2,%3}, [%4];\n"
                 : "=r"(r[0]), "=r"(r[1]), "=r"(r[2]), "=r"(r[3]) : "r"(addr));
}
__device__ __forceinline__ uint32_t packbf(float a, float b)
{
    __nv_bfloat162 h = __floats2bfloat162_rn(a, b);
    return *(uint32_t*)&h;
}
__device__ __forceinline__ uint32_t packh(float a, float b)
{
    __half2 h = __floats2half2_rn(a, b);
    return *(uint32_t*)&h;
}
__device__ __forceinline__ void cp16h(__half* dst, const __half* src)
{
    uint32_t d = (uint32_t)__cvta_generic_to_shared(dst);
    asm volatile("cp.async.cg.shared.global [%0], [%1], 16;\n" :: "r"(d), "l"(src));
}
__device__ __forceinline__ void cp_commit() { asm volatile("cp.async.commit_group;\n"); }
__device__ __forceinline__ void cp_wait1()  { asm volatile("cp.async.wait_group 1;\n"); }
__device__ __forceinline__ void cp_wait0()  { asm volatile("cp.async.wait_group 0;\n"); }

// ---------------------------------------------------------------------------
// Split fp32 -> fp16 hi + fp16 lo
// ---------------------------------------------------------------------------
__global__ __launch_bounds__(256)
void split_kernel(const float* __restrict__ in, __half* __restrict__ hi,
                  __half* __restrict__ lo, int n4)
{
    int i = blockIdx.x * 256 + threadIdx.x;
    if (i >= n4) return;
    float4 v = ((const float4*)in)[i];
    __half h0 = __float2half_rn(v.x);
    __half h1 = __float2half_rn(v.y);
    __half h2 = __float2half_rn(v.z);
    __half h3 = __float2half_rn(v.w);
    __half l0 = __float2half_rn(v.x - __half2float(h0));
    __half l1 = __float2half_rn(v.y - __half2float(h1));
    __half l2 = __float2half_rn(v.z - __half2float(h2));
    __half l3 = __float2half_rn(v.w - __half2float(h3));
    union { __half b[4]; uint2 u; } ph, pl;
    ph.b[0] = h0; ph.b[1] = h1; ph.b[2] = h2; ph.b[3] = h3;
    pl.b[0] = l0; pl.b[1] = l1; pl.b[2] = l2; pl.b[3] = l3;
    ((uint2*)hi)[i] = ph.u;
    ((uint2*)lo)[i] = pl.u;
}

// ---------------------------------------------------------------------------
// Tensor-core GEMM, fp16 2-term split: C = (Ahi+Alo) @ Bhi^T  (A-residual only)
// Block 128x128, K-tile 32, 8 warps (4m x 2n), 2-stage cp.async, ldmatrix.
// MODE 0: single output + bias.  MODE 1: fused QKV (N=3072), elu+1 on q,k.
// ---------------------------------------------------------------------------
#define SROW 40
#define STAGE_ELEMS (3 * 128 * SROW)     // Ahi, Alo, Bhi
#define GEMM_SMEM (2 * STAGE_ELEMS * 2)

template <int MODE>
__global__ __launch_bounds__(256, 2)
void gemm_f16split(const __half* __restrict__ Ahi, const __half* __restrict__ Alo,
                   const __half* __restrict__ Bhi,
                   const float* __restrict__ bias,
                   float* __restrict__ out0, float* __restrict__ out1, float* __restrict__ out2,
                   int M, int N, int K)
{
    extern __shared__ __half smem[];

    const int tid  = threadIdx.x;
    const int bm   = blockIdx.y * 128;
    const int bn   = blockIdx.x * 128;
    const int warp = tid >> 5, lane = tid & 31;
    const int wm   = (warp & 3) * 32;
    const int wn   = (warp >> 2) * 64;
    const int gid  = lane >> 2;
    const int tig  = lane & 3;

    const int KT = K / 32;

    __half* stage0 = smem;
    __half* stage1 = smem + STAGE_ELEMS;
    const uint32_t st0s = (uint32_t)__cvta_generic_to_shared(stage0);
    const uint32_t st1s = st0s + STAGE_ELEMS * 2;
    const uint32_t ALO_OFF = 128 * SROW * 2;
    const uint32_t BHI_OFF = 2 * 128 * SROW * 2;

    const int lidx = lane & 7;
    const int lmat = lane >> 3;
    int aoff[2];
#pragma unroll
    for (int mi = 0; mi < 2; mi++)
        aoff[mi] = (wm + mi * 16 + ((lmat & 1) << 3) + lidx) * SROW + ((lmat >> 1) << 3);
    int boff[4];
#pragma unroll
    for (int p = 0; p < 4; p++)
        boff[p] = (wn + p * 16 + ((lmat >> 1) << 3) + lidx) * SROW + ((lmat & 1) << 3);

    auto issue = [&](int kt, int s) {
        __half* sAh = s ? stage1 : stage0;
        __half* sAl = sAh + 128 * SROW;
        __half* sBh = sAl + 128 * SROW;
        const int kbase = kt * 32;
#pragma unroll
        for (int c = 0; c < 2; c++) {
            int q   = tid + c * 256;
            int row = q >> 2;
            int kc  = (q & 3) << 3;
            const size_t ga = (size_t)(bm + row) * K + kbase + kc;
            const size_t gb = (size_t)(bn + row) * K + kbase + kc;
            cp16h(sAh + row * SROW + kc, Ahi + ga);
            cp16h(sAl + row * SROW + kc, Alo + ga);
            cp16h(sBh + row * SROW + kc, Bhi + gb);
        }
        cp_commit();
    };

    float acc[2][8][4];
#pragma unroll
    for (int mi = 0; mi < 2; mi++)
#pragma unroll
        for (int ni = 0; ni < 8; ni++)
#pragma unroll
            for (int j = 0; j < 4; j++) acc[mi][ni][j] = 0.f;

    issue(0, 0);
    issue(1, 1);

    for (int kt = 0; kt < KT; kt++) {
        if (kt + 1 < KT) cp_wait1(); else cp_wait0();
        __syncthreads();

        const uint32_t sb = (kt & 1) ? st1s : st0s;

#pragma unroll
        for (int ks = 0; ks < 2; ks++) {
            const uint32_t kofs = (uint32_t)(ks * 16) * 2;
            uint32_t ahi[2][4], alo[2][4];
#pragma unroll
            for (int mi = 0; mi < 2; mi++) {
                const uint32_t ab = sb + (uint32_t)aoff[mi] * 2 + kofs;
                ldm_x4(ahi[mi], ab);
                ldm_x4(alo[mi], ab + ALO_OFF);
            }
#pragma unroll
            for (int p = 0; p < 4; p++) {
                uint32_t bh4[4];
                const uint32_t bb = sb + BHI_OFF + (uint32_t)boff[p] * 2 + kofs;
                ldm_x4(bh4, bb);
#pragma unroll
                for (int sub = 0; sub < 2; sub++) {
                    const uint32_t bh2[2] = { bh4[sub * 2], bh4[sub * 2 + 1] };
                    const int ni = p * 2 + sub;
#pragma unroll
                    for (int mi = 0; mi < 2; mi++) {
                        mma_f16(acc[mi][ni], ahi[mi], bh2);
                        mma_f16(acc[mi][ni], alo[mi], bh2);
                    }
                }
            }
        }
        __syncthreads();
        if (kt + 2 < KT) issue(kt + 2, kt & 1);
    }

    float* dst;
    int col_base, nOut;
    bool do_elu = false;
    if (MODE == 1) {
        const int seg = (int)blockIdx.x >> 3;
        dst = (seg == 0) ? out0 : (seg == 1) ? out1 : out2;
        col_base = ((int)blockIdx.x & 7) * 128;
        nOut = 1024;
        do_elu = (seg < 2);
    } else {
        dst = out0; col_base = bn; nOut = N;
    }

#pragma unroll
    for (int mi = 0; mi < 2; mi++) {
#pragma unroll
        for (int ni = 0; ni < 8; ni++) {
            const int row = bm + wm + mi * 16 + gid;
            const int col = col_base + wn + ni * 8 + tig * 2;
            float v0 = acc[mi][ni][0], v1 = acc[mi][ni][1];
            float v2 = acc[mi][ni][2], v3 = acc[mi][ni][3];
            if (MODE == 1) {
                if (do_elu) {
                    v0 = (v0 > 0.f) ? (v0 + 1.f) : expf(v0);
                    v1 = (v1 > 0.f) ? (v1 + 1.f) : expf(v1);
                    v2 = (v2 > 0.f) ? (v2 + 1.f) : expf(v2);
                    v3 = (v3 > 0.f) ? (v3 + 1.f) : expf(v3);
                }
            } else {
                v0 += bias[col]; v1 += bias[col + 1];
                v2 += bias[col]; v3 += bias[col + 1];
            }
            *(float2*)(dst + (size_t)row * nOut + col)       = make_float2(v0, v1);
            *(float2*)(dst + (size_t)(row + 8) * nOut + col) = make_float2(v2, v3);
        }
    }
}

// ---------------------------------------------------------------------------
// Chunk-local states (unchanged, verified)
// ---------------------------------------------------------------------------
__global__ __launch_bounds__(256)
void chunk_local_kernel(const float* __restrict__ pk, const float* __restrict__ vv,
                        float* __restrict__ Sloc, float* __restrict__ zloc)
{
    extern __shared__ float sm[];
    float* Pks = sm;
    float* Vs  = sm + C_ * D_;

    const int c = blockIdx.x, h = blockIdx.y, b = blockIdx.z;
    const size_t base = ((size_t)b * L_ + (size_t)c * C_) * E_ + (size_t)h * D_;
    const float* pkb = pk + base;
    const float* vb  = vv + base;

    for (int i = threadIdx.x; i < C_ * D_ / 4; i += 256) {
        const int row = i >> 4;
        const int c4  = (i & 15) << 2;
        *(float4*)&Pks[row * D_ + c4] = *(const float4*)(pkb + (size_t)row * E_ + c4);
        *(float4*)&Vs [row * D_ + c4] = *(const float4*)(vb  + (size_t)row * E_ + c4);
    }
    __syncthreads();

    const int ty = threadIdx.x >> 4, tx = threadIdx.x & 15;
    float acc[4][4];
#pragma unroll
    for (int i = 0; i < 4; i++)
#pragma unroll
        for (int j = 0; j < 4; j++) acc[i][j] = 0.f;

#pragma unroll 4
    for (int t = 0; t < C_; t++) {
        float a[4], bb[4];
#pragma unroll
        for (int i = 0; i < 4; i++) a[i]  = Pks[t * D_ + ty * 4 + i];
#pragma unroll
        for (int j = 0; j < 4; j++) bb[j] = Vs [t * D_ + tx * 4 + j];
#pragma unroll
        for (int i = 0; i < 4; i++)
#pragma unroll
            for (int j = 0; j < 4; j++) acc[i][j] += a[i] * bb[j];
    }

    float* Sout = Sloc + ((((size_t)b * H_ + h) * NC_ + c) * D_ * D_);
#pragma unroll
    for (int i = 0; i < 4; i++)
#pragma unroll
        for (int j = 0; j < 4; j++)
            Sout[(ty * 4 + i) * D_ + tx * 4 + j] = acc[i][j];

    if (threadIdx.x < D_) {
        float s = 0.f;
#pragma unroll 8
        for (int t = 0; t < C_; t++) s += Pks[t * D_ + threadIdx.x];
        zloc[(((size_t)b * H_ + h) * NC_ + c) * D_ + threadIdx.x] = s;
    }
}

// ---------------------------------------------------------------------------
// Exclusive prefix over chunks (unchanged)
// ---------------------------------------------------------------------------
__global__ __launch_bounds__(256)
void prefix_kernel(float* __restrict__ S, float* __restrict__ z)
{
    const int bh = blockIdx.x;
    float* Sb = S + (size_t)bh * NC_ * D_ * D_;
    float* zb = z + (size_t)bh * NC_ * D_;

    for (int i = threadIdx.x; i < D_ * D_ / 4; i += 256) {
        float4 run = make_float4(0.f, 0.f, 0.f, 0.f);
        for (int c = 0; c < NC_; c++) {
            float4* p = (float4*)&Sb[(size_t)c * D_ * D_ + i * 4];
            float4 loc = *p;
            *p = run;
            run.x += loc.x; run.y += loc.y; run.z += loc.z; run.w += loc.w;
        }
    }
    for (int i = threadIdx.x; i < D_; i += 256) {
        float run = 0.f;
        for (int c = 0; c < NC_; c++) {
            const float loc = zb[(size_t)c * D_ + i];
            zb[(size_t)c * D_ + i] = run;
            run += loc;
        }
    }
}

// ---------------------------------------------------------------------------
// Chunk output (tensor-core mma.sync bf16 3-term, verified R7 internals;
// epilogue emits fp16 hi/lo for the out-projection)
// ---------------------------------------------------------------------------
#define QROW 72
#define OFF_QHI 0
#define OFF_QLO (OFF_QHI + 128 * QROW)
#define OFF_KHI (OFF_QLO + 128 * QROW)
#define OFF_KLO (OFF_KHI + 128 * QROW)
#define OFF_VHI (OFF_KLO + 128 * QROW)
#define OFF_VLO (OFF_VHI + 128 * QROW)
#define OFF_STHI (OFF_VLO + 128 * QROW)
#define OFF_STLO (OFF_STHI + 64 * QROW)
#define OFF_Z    (OFF_STLO + 64 * QROW)
#define CO_SMEM ((OFF_Z + 128) * 2)

__global__ __launch_bounds__(256)
void chunk_out_kernel(const float* __restrict__ pq, const float* __restrict__ pk,
                      const float* __restrict__ vv, const float* __restrict__ S,
                      const float* __restrict__ z,
                      __half* __restrict__ attn_hi,
                      __half* __restrict__ attn_lo)
{
    extern __shared__ __nv_bfloat16 cs[];
    const uint32_t sbase = (uint32_t)__cvta_generic_to_shared(cs);

    const int tid  = threadIdx.x;
    const int warp = tid >> 5, lane = tid & 31;
    const int g    = lane >> 2, t = lane & 3;
    const int lidx = lane & 7,  lmat = lane >> 3;

    const int c = blockIdx.x, h = blockIdx.y, b = blockIdx.z;
    const size_t base = ((size_t)b * L_ + (size_t)c * C_) * E_ + (size_t)h * D_;
    const float* pqb = pq + base;
    const float* pkb = pk + base;
    const float* vb  = vv + base;

    for (int i = tid; i < 128 * 16; i += 256) {
        const int row = i >> 4;
        const int c4  = (i & 15) << 2;
        float4 qv = *(const float4*)(pqb + (size_t)row * E_ + c4);
        float4 kv = *(const float4*)(pkb + (size_t)row * E_ + c4);
        float4 wv = *(const float4*)(vb  + (size_t)row * E_ + c4);
        const float* vals[3] = { (float*)&qv, (float*)&kv, (float*)&wv };
        const int offs_hi[3] = { OFF_QHI, OFF_KHI, OFF_VHI };
        const int offs_lo[3] = { OFF_QLO, OFF_KLO, OFF_VLO };
#pragma unroll
        for (int p = 0; p < 3; p++) {
            union { __nv_bfloat16 bx[4]; uint2 u; } ph, pl;
#pragma unroll
            for (int j = 0; j < 4; j++) {
                float v = vals[p][j];
                __nv_bfloat16 hb = __float2bfloat16(v);
                ph.bx[j] = hb;
                pl.bx[j] = __float2bfloat16(v - __bfloat162float(hb));
            }
            *(uint2*)&cs[offs_hi[p] + row * QROW + c4] = ph.u;
            *(uint2*)&cs[offs_lo[p] + row * QROW + c4] = pl.u;
        }
    }
    {
        const float* Sb = S + (((size_t)b * H_ + h) * NC_ + c) * D_ * D_;
        for (int i = tid; i < 64 * 16; i += 256) {
            const int r  = i >> 4;
            const int c4 = (i & 15) << 2;
            float4 sv = *(const float4*)(Sb + (size_t)r * D_ + c4);
            const float* sp = (const float*)&sv;
#pragma unroll
            for (int j = 0; j < 4; j++) {
                const int col = c4 + j;
                float v = sp[j];
                __nv_bfloat16 hb = __float2bfloat16(v);
                cs[OFF_STHI + col * QROW + r] = hb;
                cs[OFF_STLO + col * QROW + r] = __float2bfloat16(v - __bfloat162float(hb));
            }
        }
        if (tid < 64) {
            const float* zbp = z + (((size_t)b * H_ + h) * NC_ + c) * D_;
            ((float*)(cs + OFF_Z))[tid] = zbp[tid];
        }
    }
    __syncthreads();

    const uint32_t aoff_b =
        (uint32_t)(((16 * warp + ((lmat & 1) << 3) + lidx) * QROW + ((lmat >> 1) << 3)) * 2);

    float mC[16][4];
#pragma unroll
    for (int j = 0; j < 16; j++)
#pragma unroll
        for (int q = 0; q < 4; q++) mC[j][q] = 0.f;

#pragma unroll
    for (int ks = 0; ks < 4; ks++) {
        uint32_t aqh[4], aql[4];
        const uint32_t qa = sbase + OFF_QHI * 2 + aoff_b + ks * 32;
        ldm_x4(aqh, qa);
        ldm_x4(aql, qa + (OFF_QLO - OFF_QHI) * 2);
#pragma unroll
        for (int p = 0; p < 8; p++) {
            const uint32_t bb = sbase + OFF_KHI * 2 +
                (uint32_t)(((p * 16 + ((lmat >> 1) << 3) + lidx) * QROW + ((lmat & 1) << 3)) * 2)
                + ks * 32;
            uint32_t bh4[4], bl4[4];
            ldm_x4(bh4, bb);
            ldm_x4(bl4, bb + (OFF_KLO - OFF_KHI) * 2);
#pragma unroll
            for (int sub = 0; sub < 2; sub++) {
                const uint32_t bh2[2] = { bh4[sub * 2], bh4[sub * 2 + 1] };
                const uint32_t bl2[2] = { bl4[sub * 2], bl4[sub * 2 + 1] };
                mma_bf16(mC[2 * p + sub], aqh, bh2);
                mma_bf16(mC[2 * p + sub], aqh, bl2);
                mma_bf16(mC[2 * p + sub], aql, bh2);
            }
        }
    }

    const int row0 = 16 * warp + g;
    const int row1 = row0 + 8;
    float pg = 0.f, pg8 = 0.f;
#pragma unroll
    for (int j = 0; j < 16; j++) {
        const int c0 = 8 * j + 2 * t;
        if (c0 > row0)     mC[j][0] = 0.f;
        if (c0 + 1 > row0) mC[j][1] = 0.f;
        if (c0 > row1)     mC[j][2] = 0.f;
        if (c0 + 1 > row1) mC[j][3] = 0.f;
        pg  += mC[j][0] + mC[j][1];
        pg8 += mC[j][2] + mC[j][3];
    }

    uint32_t mh[8][4], ml[8][4];
#pragma unroll
    for (int ks = 0; ks < 8; ks++) {
#pragma unroll
        for (int q = 0; q < 4; q++) {
            const int j = 2 * ks + (q >> 1);
            const int lohalf = (q & 1) * 2;
            float v0 = mC[j][lohalf], v1 = mC[j][lohalf + 1];
            float h0 = __bfloat162float(__float2bfloat16(v0));
            float h1 = __bfloat162float(__float2bfloat16(v1));
            mh[ks][q] = packbf(h0, h1);
            ml[ks][q] = packbf(v0 - h0, v1 - h1);
        }
    }

    pg  += __shfl_xor_sync(0xffffffffu, pg, 1);
    pg  += __shfl_xor_sync(0xffffffffu, pg, 2);
    pg8 += __shfl_xor_sync(0xffffffffu, pg8, 1);
    pg8 += __shfl_xor_sync(0xffffffffu, pg8, 2);

    float dqv = 0.f;
    if (lane < 16) {
        const int r = 16 * warp + lane;
        const float* zf = (const float*)(cs + OFF_Z);
#pragma unroll 8
        for (int k = 0; k < 64; k++) {
            float qv = __bfloat162float(cs[OFF_QHI + r * QROW + k]) +
                       __bfloat162float(cs[OFF_QLO + r * QROW + k]);
            dqv += qv * zf[k];
        }
    }
    const float dq0 = __shfl_sync(0xffffffffu, dqv, g);
    const float dq8 = __shfl_sync(0xffffffffu, dqv, g + 8);
    const float rs0 = 1.f / (pg  + dq0 + EPS_);
    const float rs1 = 1.f / (pg8 + dq8 + EPS_);

    float acc[8][4];
#pragma unroll
    for (int nt = 0; nt < 8; nt++)
#pragma unroll
        for (int q = 0; q < 4; q++) acc[nt][q] = 0.f;

#pragma unroll
    for (int ks = 0; ks < 4; ks++) {
        uint32_t aqh[4], aql[4];
        const uint32_t qa = sbase + OFF_QHI * 2 + aoff_b + ks * 32;
        ldm_x4(aqh, qa);
        ldm_x4(aql, qa + (OFF_QLO - OFF_QHI) * 2);
#pragma unroll
        for (int p = 0; p < 4; p++) {
            const uint32_t bb = sbase + OFF_STHI * 2 +
                (uint32_t)(((p * 16 + ((lmat >> 1) << 3) + lidx) * QROW + ((lmat & 1) << 3)) * 2)
                + ks * 32;
            uint32_t bh4[4], bl4[4];
            ldm_x4(bh4, bb);
            ldm_x4(bl4, bb + (OFF_STLO - OFF_STHI) * 2);
#pragma unroll
            for (int sub = 0; sub < 2; sub++) {
                const uint32_t bh2[2] = { bh4[sub * 2], bh4[sub * 2 + 1] };
                const uint32_t bl2[2] = { bl4[sub * 2], bl4[sub * 2 + 1] };
                mma_bf16(acc[2 * p + sub], aqh, bh2);
                mma_bf16(acc[2 * p + sub], aqh, bl2);
                mma_bf16(acc[2 * p + sub], aql, bh2);
            }
        }
    }

#pragma unroll
    for (int kb = 0; kb < 4; kb++) {
        const int k0e = kb * 32;
        const int ks  = kb * 2;
#pragma unroll
        for (int nt = 0; nt < 8; nt++) {
            const uint32_t va = sbase + OFF_VHI * 2 +
                (uint32_t)(((k0e + lmat * 8 + lidx) * QROW) * 2) + nt * 16;
            uint32_t vh[4], vl[4];
            ldm_x4t(vh, va);
            ldm_x4t(vl, va + (OFF_VLO - OFF_VHI) * 2);
#pragma unroll
            for (int sub = 0; sub < 2; sub++) {
                const uint32_t bh2[2] = { vh[sub * 2], vh[sub * 2 + 1] };
                const uint32_t bl2[2] = { vl[sub * 2], vl[sub * 2 + 1] };
                mma_bf16(acc[nt], mh[ks + sub], bh2);
                mma_bf16(acc[nt], mh[ks + sub], bl2);
                mma_bf16(acc[nt], ml[ks + sub], bh2);
            }
        }
    }

    // epilogue: scale by 1/den, emit fp16 hi/lo
    __half* obh = attn_hi + base;
    __half* obl = attn_lo + base;
#pragma unroll
    for (int nt = 0; nt < 8; nt++) {
        const int col = 8 * nt + 2 * t;
        float v0 = acc[nt][0] * rs0, v1 = acc[nt][1] * rs0;
        float v2 = acc[nt][2] * rs1, v3 = acc[nt][3] * rs1;
        float h0 = __half2float(__float2half_rn(v0));
        float h1 = __half2float(__float2half_rn(v1));
        float h2 = __half2float(__float2half_rn(v2));
        float h3 = __half2float(__float2half_rn(v3));
        *(uint32_t*)(obh + (size_t)row0 * E_ + col) = packh(h0, h1);
        *(uint32_t*)(obl + (size_t)row0 * E_ + col) = packh(v0 - h0, v1 - h1);
        *(uint32_t*)(obh + (size_t)row1 * E_ + col) = packh(h2, h3);
        *(uint32_t*)(obl + (size_t)row1 * E_ + col) = packh(v2 - h2, v3 - h3);
    }
}

// ---------------------------------------------------------------------------
// Launch
// ---------------------------------------------------------------------------
extern "C" void kernel_launch(void* const* d_in, const int* in_sizes, int n_in,
                              void* d_out, int out_size)
{
    const float* x  = (const float*)d_in[0];
    const float* Wq = (const float*)d_in[1];
    const float* Wk = (const float*)d_in[2];
    const float* Wv = (const float*)d_in[3];
    const float* Wo = (const float*)d_in[4];
    const float* bo = (const float*)d_in[5];
    float* out = (float*)d_out;

    float *phi_q, *phi_k, *vbuf, *Sb, *zb;
    __half *xhi, *xlo, *ahi, *alo, *whi;
    cudaGetSymbolAddress((void**)&phi_q, g_phi_q);
    cudaGetSymbolAddress((void**)&phi_k, g_phi_k);
    cudaGetSymbolAddress((void**)&vbuf,  g_v);
    cudaGetSymbolAddress((void**)&Sb,    g_S);
    cudaGetSymbolAddress((void**)&zb,    g_z);
    cudaGetSymbolAddress((void**)&xhi,   g_x_hi);
    cudaGetSymbolAddress((void**)&xlo,   g_x_lo);
    cudaGetSymbolAddress((void**)&ahi,   g_attn_hi);
    cudaGetSymbolAddress((void**)&alo,   g_attn_lo);
    cudaGetSymbolAddress((void**)&whi,   g_w_hi);

    const int sm_local = 2 * C_ * D_ * (int)sizeof(float);
    (void)cudaFuncSetAttribute(chunk_local_kernel,
                               cudaFuncAttributeMaxDynamicSharedMemorySize, sm_local);
    (void)cudaFuncSetAttribute(chunk_out_kernel,
                               cudaFuncAttributeMaxDynamicSharedMemorySize, CO_SMEM);
    (void)cudaFuncSetAttribute(gemm_f16split<0>,
                               cudaFuncAttributeMaxDynamicSharedMemorySize, GEMM_SMEM);
    (void)cudaFuncSetAttribute(gemm_f16split<1>,
                               cudaFuncAttributeMaxDynamicSharedMemorySize, GEMM_SMEM);

    // ---- split inputs to fp16 hi/lo (W residual is discarded into scratch
    //      that chunk_out overwrites before the out-projection reads it) ----
    const int nx4 = (MTOT * E_) / 4;
    split_kernel<<<(nx4 + 255) / 256, 256>>>(x, xhi, xlo, nx4);
    const int nw4 = (E_ * E_) / 4;
    const size_t wsz = (size_t)E_ * E_;
    split_kernel<<<(nw4 + 255) / 256, 256>>>(Wq, whi + 0 * wsz, alo, nw4);
    split_kernel<<<(nw4 + 255) / 256, 256>>>(Wk, whi + 1 * wsz, alo, nw4);
    split_kernel<<<(nw4 + 255) / 256, 256>>>(Wv, whi + 2 * wsz, alo, nw4);
    split_kernel<<<(nw4 + 255) / 256, 256>>>(Wo, whi + 3 * wsz, alo, nw4);

    // ---- fused QKV projection (tensor core fp16 2-term): N = 3072 ----
    dim3 gqkv(3 * E_ / 128, MTOT / 128), gb(256);
    gemm_f16split<1><<<gqkv, gb, GEMM_SMEM>>>(xhi, xlo, whi, nullptr,
                                              phi_q, phi_k, vbuf, MTOT, 3 * E_, E_);

    // ---- chunked linear attention ----
    dim3 gc(NC_, H_, B_);
    chunk_local_kernel<<<gc, 256, sm_local>>>(phi_k, vbuf, Sb, zb);
    prefix_kernel<<<B_ * H_, 256>>>(Sb, zb);
    chunk_out_kernel<<<gc, 256, CO_SMEM>>>(phi_q, phi_k, vbuf, Sb, zb, ahi, alo);

    // ---- output projection + bias ----
    dim3 gout(E_ / 128, MTOT / 128);
    gemm_f16split<0><<<gout, gb, GEMM_SMEM>>>(ahi, alo, whi + 3 * wsz,
                                              bo, out, nullptr, nullptr, MTOT, E_, E_);
}

// round 11
// speedup vs baseline: 3.7065x; 1.0969x over previous
#include <cuda_runtime.h>
#include <cuda_fp16.h>
#include <cuda_bf16.h>
#include <cstdint>
#include <cstddef>

// Problem constants
#define B_   4
#define L_   4096
#define E_   1024
#define H_   16
#define D_   64
#define C_   128
#define NC_  (L_ / C_)
#define MTOT (B_ * L_)
#define EPS_ 1e-5f

// ---------------------------------------------------------------------------
// Scratch
// ---------------------------------------------------------------------------
__device__ float g_phi_q[(size_t)B_ * L_ * E_];
__device__ float g_phi_k[(size_t)B_ * L_ * E_];
__device__ float g_v    [(size_t)B_ * L_ * E_];
__device__ float g_S[(size_t)B_ * H_ * NC_ * D_ * D_];
__device__ float g_z[(size_t)B_ * H_ * NC_ * D_];

// fp16 split buffers (only the A-side residual is consumed by the GEMMs)
__device__ __half g_x_hi[(size_t)MTOT * E_];
__device__ __half g_x_lo[(size_t)MTOT * E_];
__device__ __half g_attn_hi[(size_t)MTOT * E_];
__device__ __half g_attn_lo[(size_t)MTOT * E_];
__device__ __half g_w_hi[4][(size_t)E_ * E_];   // q,k,v contiguous = [3072][1024]

// ---------------------------------------------------------------------------
// PTX helpers
// ---------------------------------------------------------------------------
__device__ __forceinline__ void mma_f16(float* c, const uint32_t* a, const uint32_t* b)
{
    asm volatile(
        "mma.sync.aligned.m16n8k16.row.col.f32.f16.f16.f32 "
        "{%0,%1,%2,%3}, {%4,%5,%6,%7}, {%8,%9}, {%0,%1,%2,%3};\n"
        : "+f"(c[0]), "+f"(c[1]), "+f"(c[2]), "+f"(c[3])
        : "r"(a[0]), "r"(a[1]), "r"(a[2]), "r"(a[3]), "r"(b[0]), "r"(b[1]));
}

__device__ __forceinline__ void ldm_x4(uint32_t* r, uint32_t addr)
{
    asm volatile("ldmatrix.sync.aligned.m8n8.x4.shared.b16 {%0,%1,%2,%3}, [%4];\n"
                 : "=r"(r[0]), "=r"(r[1]), "=r"(r[2]), "=r"(r[3]) : "r"(addr));
}
__device__ __forceinline__ void ldm_x2t(uint32_t* r, uint32_t addr)
{
    asm volatile("ldmatrix.sync.aligned.m8n8.x2.trans.shared.b16 {%0,%1}, [%2];\n"
                 : "=r"(r[0]), "=r"(r[1]) : "r"(addr));
}
__device__ __forceinline__ uint32_t packh(float a, float b)
{
    __half2 h = __floats2half2_rn(a, b);
    return *(uint32_t*)&h;
}
__device__ __forceinline__ void cp16h(__half* dst, const __half* src)
{
    uint32_t d = (uint32_t)__cvta_generic_to_shared(dst);
    asm volatile("cp.async.cg.shared.global [%0], [%1], 16;\n" :: "r"(d), "l"(src));
}
__device__ __forceinline__ void cp_commit() { asm volatile("cp.async.commit_group;\n"); }
__device__ __forceinline__ void cp_wait1()  { asm volatile("cp.async.wait_group 1;\n"); }
__device__ __forceinline__ void cp_wait0()  { asm volatile("cp.async.wait_group 0;\n"); }

// ---------------------------------------------------------------------------
// Split fp32 -> fp16 hi + fp16 lo
// ---------------------------------------------------------------------------
__global__ __launch_bounds__(256)
void split_kernel(const float* __restrict__ in, __half* __restrict__ hi,
                  __half* __restrict__ lo, int n4)
{
    int i = blockIdx.x * 256 + threadIdx.x;
    if (i >= n4) return;
    float4 v = ((const float4*)in)[i];
    __half h0 = __float2half_rn(v.x);
    __half h1 = __float2half_rn(v.y);
    __half h2 = __float2half_rn(v.z);
    __half h3 = __float2half_rn(v.w);
    __half l0 = __float2half_rn(v.x - __half2float(h0));
    __half l1 = __float2half_rn(v.y - __half2float(h1));
    __half l2 = __float2half_rn(v.z - __half2float(h2));
    __half l3 = __float2half_rn(v.w - __half2float(h3));
    union { __half b[4]; uint2 u; } ph, pl;
    ph.b[0] = h0; ph.b[1] = h1; ph.b[2] = h2; ph.b[3] = h3;
    pl.b[0] = l0; pl.b[1] = l1; pl.b[2] = l2; pl.b[3] = l3;
    ((uint2*)hi)[i] = ph.u;
    ((uint2*)lo)[i] = pl.u;
}

// ---------------------------------------------------------------------------
// Tensor-core GEMM, fp16 2-term split: C = (Ahi+Alo) @ Bhi^T  (verified R10)
// ---------------------------------------------------------------------------
#define SROW 40
#define STAGE_ELEMS (3 * 128 * SROW)     // Ahi, Alo, Bhi
#define GEMM_SMEM (2 * STAGE_ELEMS * 2)

template <int MODE>
__global__ __launch_bounds__(256, 2)
void gemm_f16split(const __half* __restrict__ Ahi, const __half* __restrict__ Alo,
                   const __half* __restrict__ Bhi,
                   const float* __restrict__ bias,
                   float* __restrict__ out0, float* __restrict__ out1, float* __restrict__ out2,
                   int M, int N, int K)
{
    extern __shared__ __half smem[];

    const int tid  = threadIdx.x;
    const int bm   = blockIdx.y * 128;
    const int bn   = blockIdx.x * 128;
    const int warp = tid >> 5, lane = tid & 31;
    const int wm   = (warp & 3) * 32;
    const int wn   = (warp >> 2) * 64;
    const int gid  = lane >> 2;
    const int tig  = lane & 3;

    const int KT = K / 32;

    __half* stage0 = smem;
    __half* stage1 = smem + STAGE_ELEMS;
    const uint32_t st0s = (uint32_t)__cvta_generic_to_shared(stage0);
    const uint32_t st1s = st0s + STAGE_ELEMS * 2;
    const uint32_t ALO_OFF = 128 * SROW * 2;
    const uint32_t BHI_OFF = 2 * 128 * SROW * 2;

    const int lidx = lane & 7;
    const int lmat = lane >> 3;
    int aoff[2];
#pragma unroll
    for (int mi = 0; mi < 2; mi++)
        aoff[mi] = (wm + mi * 16 + ((lmat & 1) << 3) + lidx) * SROW + ((lmat >> 1) << 3);
    int boff[4];
#pragma unroll
    for (int p = 0; p < 4; p++)
        boff[p] = (wn + p * 16 + ((lmat >> 1) << 3) + lidx) * SROW + ((lmat & 1) << 3);

    auto issue = [&](int kt, int s) {
        __half* sAh = s ? stage1 : stage0;
        __half* sAl = sAh + 128 * SROW;
        __half* sBh = sAl + 128 * SROW;
        const int kbase = kt * 32;
#pragma unroll
        for (int c = 0; c < 2; c++) {
            int q   = tid + c * 256;
            int row = q >> 2;
            int kc  = (q & 3) << 3;
            const size_t ga = (size_t)(bm + row) * K + kbase + kc;
            const size_t gb = (size_t)(bn + row) * K + kbase + kc;
            cp16h(sAh + row * SROW + kc, Ahi + ga);
            cp16h(sAl + row * SROW + kc, Alo + ga);
            cp16h(sBh + row * SROW + kc, Bhi + gb);
        }
        cp_commit();
    };

    float acc[2][8][4];
#pragma unroll
    for (int mi = 0; mi < 2; mi++)
#pragma unroll
        for (int ni = 0; ni < 8; ni++)
#pragma unroll
            for (int j = 0; j < 4; j++) acc[mi][ni][j] = 0.f;

    issue(0, 0);
    issue(1, 1);

    for (int kt = 0; kt < KT; kt++) {
        if (kt + 1 < KT) cp_wait1(); else cp_wait0();
        __syncthreads();

        const uint32_t sb = (kt & 1) ? st1s : st0s;

#pragma unroll
        for (int ks = 0; ks < 2; ks++) {
            const uint32_t kofs = (uint32_t)(ks * 16) * 2;
            uint32_t ahi[2][4], alo[2][4];
#pragma unroll
            for (int mi = 0; mi < 2; mi++) {
                const uint32_t ab = sb + (uint32_t)aoff[mi] * 2 + kofs;
                ldm_x4(ahi[mi], ab);
                ldm_x4(alo[mi], ab + ALO_OFF);
            }
#pragma unroll
            for (int p = 0; p < 4; p++) {
                uint32_t bh4[4];
                const uint32_t bb = sb + BHI_OFF + (uint32_t)boff[p] * 2 + kofs;
                ldm_x4(bh4, bb);
#pragma unroll
                for (int sub = 0; sub < 2; sub++) {
                    const uint32_t bh2[2] = { bh4[sub * 2], bh4[sub * 2 + 1] };
                    const int ni = p * 2 + sub;
#pragma unroll
                    for (int mi = 0; mi < 2; mi++) {
                        mma_f16(acc[mi][ni], ahi[mi], bh2);
                        mma_f16(acc[mi][ni], alo[mi], bh2);
                    }
                }
            }
        }
        __syncthreads();
        if (kt + 2 < KT) issue(kt + 2, kt & 1);
    }

    float* dst;
    int col_base, nOut;
    bool do_elu = false;
    if (MODE == 1) {
        const int seg = (int)blockIdx.x >> 3;
        dst = (seg == 0) ? out0 : (seg == 1) ? out1 : out2;
        col_base = ((int)blockIdx.x & 7) * 128;
        nOut = 1024;
        do_elu = (seg < 2);
    } else {
        dst = out0; col_base = bn; nOut = N;
    }

#pragma unroll
    for (int mi = 0; mi < 2; mi++) {
#pragma unroll
        for (int ni = 0; ni < 8; ni++) {
            const int row = bm + wm + mi * 16 + gid;
            const int col = col_base + wn + ni * 8 + tig * 2;
            float v0 = acc[mi][ni][0], v1 = acc[mi][ni][1];
            float v2 = acc[mi][ni][2], v3 = acc[mi][ni][3];
            if (MODE == 1) {
                if (do_elu) {
                    v0 = (v0 > 0.f) ? (v0 + 1.f) : expf(v0);
                    v1 = (v1 > 0.f) ? (v1 + 1.f) : expf(v1);
                    v2 = (v2 > 0.f) ? (v2 + 1.f) : expf(v2);
                    v3 = (v3 > 0.f) ? (v3 + 1.f) : expf(v3);
                }
            } else {
                v0 += bias[col]; v1 += bias[col + 1];
                v2 += bias[col]; v3 += bias[col + 1];
            }
            *(float2*)(dst + (size_t)row * nOut + col)       = make_float2(v0, v1);
            *(float2*)(dst + (size_t)(row + 8) * nOut + col) = make_float2(v2, v3);
        }
    }
}

// ---------------------------------------------------------------------------
// Chunk-local states (unchanged, verified)
// ---------------------------------------------------------------------------
__global__ __launch_bounds__(256)
void chunk_local_kernel(const float* __restrict__ pk, const float* __restrict__ vv,
                        float* __restrict__ Sloc, float* __restrict__ zloc)
{
    extern __shared__ float sm[];
    float* Pks = sm;
    float* Vs  = sm + C_ * D_;

    const int c = blockIdx.x, h = blockIdx.y, b = blockIdx.z;
    const size_t base = ((size_t)b * L_ + (size_t)c * C_) * E_ + (size_t)h * D_;
    const float* pkb = pk + base;
    const float* vb  = vv + base;

    for (int i = threadIdx.x; i < C_ * D_ / 4; i += 256) {
        const int row = i >> 4;
        const int c4  = (i & 15) << 2;
        *(float4*)&Pks[row * D_ + c4] = *(const float4*)(pkb + (size_t)row * E_ + c4);
        *(float4*)&Vs [row * D_ + c4] = *(const float4*)(vb  + (size_t)row * E_ + c4);
    }
    __syncthreads();

    const int ty = threadIdx.x >> 4, tx = threadIdx.x & 15;
    float acc[4][4];
#pragma unroll
    for (int i = 0; i < 4; i++)
#pragma unroll
        for (int j = 0; j < 4; j++) acc[i][j] = 0.f;

#pragma unroll 4
    for (int t = 0; t < C_; t++) {
        float a[4], bb[4];
#pragma unroll
        for (int i = 0; i < 4; i++) a[i]  = Pks[t * D_ + ty * 4 + i];
#pragma unroll
        for (int j = 0; j < 4; j++) bb[j] = Vs [t * D_ + tx * 4 + j];
#pragma unroll
        for (int i = 0; i < 4; i++)
#pragma unroll
            for (int j = 0; j < 4; j++) acc[i][j] += a[i] * bb[j];
    }

    float* Sout = Sloc + ((((size_t)b * H_ + h) * NC_ + c) * D_ * D_);
#pragma unroll
    for (int i = 0; i < 4; i++)
#pragma unroll
        for (int j = 0; j < 4; j++)
            Sout[(ty * 4 + i) * D_ + tx * 4 + j] = acc[i][j];

    if (threadIdx.x < D_) {
        float s = 0.f;
#pragma unroll 8
        for (int t = 0; t < C_; t++) s += Pks[t * D_ + threadIdx.x];
        zloc[(((size_t)b * H_ + h) * NC_ + c) * D_ + threadIdx.x] = s;
    }
}

// ---------------------------------------------------------------------------
// Exclusive prefix over chunks (unchanged)
// ---------------------------------------------------------------------------
__global__ __launch_bounds__(256)
void prefix_kernel(float* __restrict__ S, float* __restrict__ z)
{
    const int bh = blockIdx.x;
    float* Sb = S + (size_t)bh * NC_ * D_ * D_;
    float* zb = z + (size_t)bh * NC_ * D_;

    for (int i = threadIdx.x; i < D_ * D_ / 4; i += 256) {
        float4 run = make_float4(0.f, 0.f, 0.f, 0.f);
        for (int c = 0; c < NC_; c++) {
            float4* p = (float4*)&Sb[(size_t)c * D_ * D_ + i * 4];
            float4 loc = *p;
            *p = run;
            run.x += loc.x; run.y += loc.y; run.z += loc.z; run.w += loc.w;
        }
    }
    for (int i = threadIdx.x; i < D_; i += 256) {
        float run = 0.f;
        for (int c = 0; c < NC_; c++) {
            const float loc = zb[(size_t)c * D_ + i];
            zb[(size_t)c * D_ + i] = run;
            run += loc;
        }
    }
}

// ---------------------------------------------------------------------------
// Chunk output — fp16 2-term, causal tile skip, fused score->output loop.
//   O = (phi_q @ S + causal(phi_q @ phi_k^T) @ V) / den
// Planes (fp16): Qhi, Qlo, Khi, Vhi, SThi; z fp32. 83 KB smem -> 2 blocks/SM.
// Warp w owns rows 16w..16w+15; k-tiles p>warp are fully masked -> skipped.
// ---------------------------------------------------------------------------
#define QROW 72
#define OFF_QHI 0
#define OFF_QLO (OFF_QHI + 128 * QROW)
#define OFF_KHI (OFF_QLO + 128 * QROW)
#define OFF_VHI (OFF_KHI + 128 * QROW)
#define OFF_STHI (OFF_VHI + 128 * QROW)
#define OFF_Z    (OFF_STHI + 64 * QROW)
#define CO_SMEM ((OFF_Z + 128) * 2)

__global__ __launch_bounds__(256, 2)
void chunk_out_kernel(const float* __restrict__ pq, const float* __restrict__ pk,
                      const float* __restrict__ vv, const float* __restrict__ S,
                      const float* __restrict__ z,
                      __half* __restrict__ attn_hi,
                      __half* __restrict__ attn_lo)
{
    extern __shared__ __half cs[];
    const uint32_t sbase = (uint32_t)__cvta_generic_to_shared(cs);

    const int tid  = threadIdx.x;
    const int warp = tid >> 5, lane = tid & 31;
    const int g    = lane >> 2, t = lane & 3;
    const int lidx = lane & 7,  lmat = lane >> 3;

    const int c = blockIdx.x, h = blockIdx.y, b = blockIdx.z;
    const size_t base = ((size_t)b * L_ + (size_t)c * C_) * E_ + (size_t)h * D_;
    const float* pqb = pq + base;
    const float* pkb = pk + base;
    const float* vb  = vv + base;

    // ---- load: Q split hi/lo; K hi; V hi ----------------------------------
    for (int i = tid; i < 128 * 16; i += 256) {
        const int row = i >> 4;
        const int c4  = (i & 15) << 2;
        float4 qv = *(const float4*)(pqb + (size_t)row * E_ + c4);
        float4 kv = *(const float4*)(pkb + (size_t)row * E_ + c4);
        float4 wv = *(const float4*)(vb  + (size_t)row * E_ + c4);
        union { __half bx[4]; uint2 u; } ph, pl, pkx, pvx;
        const float* qp = (const float*)&qv;
#pragma unroll
        for (int j = 0; j < 4; j++) {
            __half hb = __float2half_rn(qp[j]);
            ph.bx[j] = hb;
            pl.bx[j] = __float2half_rn(qp[j] - __half2float(hb));
        }
        pkx.bx[0] = __float2half_rn(kv.x); pkx.bx[1] = __float2half_rn(kv.y);
        pkx.bx[2] = __float2half_rn(kv.z); pkx.bx[3] = __float2half_rn(kv.w);
        pvx.bx[0] = __float2half_rn(wv.x); pvx.bx[1] = __float2half_rn(wv.y);
        pvx.bx[2] = __float2half_rn(wv.z); pvx.bx[3] = __float2half_rn(wv.w);
        *(uint2*)&cs[OFF_QHI + row * QROW + c4] = ph.u;
        *(uint2*)&cs[OFF_QLO + row * QROW + c4] = pl.u;
        *(uint2*)&cs[OFF_KHI + row * QROW + c4] = pkx.u;
        *(uint2*)&cs[OFF_VHI + row * QROW + c4] = pvx.u;
    }
    // S (64x64) transposed hi; z fp32
    {
        const float* Sb = S + (((size_t)b * H_ + h) * NC_ + c) * D_ * D_;
        for (int i = tid; i < 64 * 16; i += 256) {
            const int r  = i >> 4;
            const int c4 = (i & 15) << 2;
            float4 sv = *(const float4*)(Sb + (size_t)r * D_ + c4);
            const float* sp = (const float*)&sv;
#pragma unroll
            for (int j = 0; j < 4; j++)
                cs[OFF_STHI + (c4 + j) * QROW + r] = __float2half_rn(sp[j]);
        }
        if (tid < 64) {
            const float* zbp = z + (((size_t)b * H_ + h) * NC_ + c) * D_;
            ((float*)(cs + OFF_Z))[tid] = zbp[tid];
        }
    }
    __syncthreads();

    // ---- cache Q A-fragments for all 4 k-steps ----------------------------
    const uint32_t aoff_b =
        (uint32_t)(((16 * warp + ((lmat & 1) << 3) + lidx) * QROW + ((lmat >> 1) << 3)) * 2);
    uint32_t aqh[4][4], aql[4][4];
#pragma unroll
    for (int ks = 0; ks < 4; ks++) {
        const uint32_t qa = sbase + OFF_QHI * 2 + aoff_b + ks * 32;
        ldm_x4(aqh[ks], qa);
        ldm_x4(aql[ks], qa + (OFF_QLO - OFF_QHI) * 2);
    }

    float acc[8][4];
#pragma unroll
    for (int nt = 0; nt < 8; nt++)
#pragma unroll
        for (int q = 0; q < 4; q++) acc[nt][q] = 0.f;

    // ---- inter-chunk: phi_q @ S (B = ST, n = 64) --------------------------
#pragma unroll
    for (int ks = 0; ks < 4; ks++) {
#pragma unroll
        for (int p4 = 0; p4 < 4; p4++) {
            const uint32_t bb = sbase + OFF_STHI * 2 +
                (uint32_t)(((p4 * 16 + ((lmat >> 1) << 3) + lidx) * QROW + ((lmat & 1) << 3)) * 2)
                + ks * 32;
            uint32_t bh4[4];
            ldm_x4(bh4, bb);
#pragma unroll
            for (int sub = 0; sub < 2; sub++) {
                const uint32_t bh2[2] = { bh4[sub * 2], bh4[sub * 2 + 1] };
                mma_f16(acc[2 * p4 + sub], aqh[ks], bh2);
                mma_f16(acc[2 * p4 + sub], aql[ks], bh2);
            }
        }
    }

    // ---- intra-chunk: causal tiles p = 0..warp ----------------------------
    const int row0 = 16 * warp + g;
    const int row1 = row0 + 8;
    float pg = 0.f, pg8 = 0.f;
    const uint32_t vrow_lane = (uint32_t)(lane & 15);

    for (int p = 0; p <= warp; p++) {
        // scores for k-tile p (cols 16p..16p+15)
        float mC2[2][4];
#pragma unroll
        for (int sub = 0; sub < 2; sub++)
#pragma unroll
            for (int q = 0; q < 4; q++) mC2[sub][q] = 0.f;

#pragma unroll
        for (int ks = 0; ks < 4; ks++) {
            const uint32_t bb = sbase + OFF_KHI * 2 +
                (uint32_t)(((p * 16 + ((lmat >> 1) << 3) + lidx) * QROW + ((lmat & 1) << 3)) * 2)
                + ks * 32;
            uint32_t bh4[4];
            ldm_x4(bh4, bb);
#pragma unroll
            for (int sub = 0; sub < 2; sub++) {
                const uint32_t bh2[2] = { bh4[sub * 2], bh4[sub * 2 + 1] };
                mma_f16(mC2[sub], aqh[ks], bh2);
                mma_f16(mC2[sub], aql[ks], bh2);
            }
        }

        // causal mask only on the diagonal tile
        if (p == warp) {
#pragma unroll
            for (int sub = 0; sub < 2; sub++) {
                const int c0 = 16 * p + 8 * sub + 2 * t;
                if (c0 > row0)     mC2[sub][0] = 0.f;
                if (c0 + 1 > row0) mC2[sub][1] = 0.f;
                if (c0 > row1)     mC2[sub][2] = 0.f;
                if (c0 + 1 > row1) mC2[sub][3] = 0.f;
            }
        }
        pg  += mC2[0][0] + mC2[0][1] + mC2[1][0] + mC2[1][1];
        pg8 += mC2[0][2] + mC2[0][3] + mC2[1][2] + mC2[1][3];

        // repack M tile into fp16 hi/lo A-fragment (k-range 16p..16p+15)
        uint32_t mh[4], ml[4];
#pragma unroll
        for (int q = 0; q < 4; q++) {
            const int sub = q >> 1;
            const int lohalf = (q & 1) * 2;
            float v0 = mC2[sub][lohalf], v1 = mC2[sub][lohalf + 1];
            float h0 = __half2float(__float2half_rn(v0));
            float h1 = __half2float(__float2half_rn(v1));
            mh[q] = packh(h0, h1);
            ml[q] = packh(v0 - h0, v1 - h1);
        }

        // M_p @ V rows 16p..16p+15 (B via ldmatrix.x2.trans)
        const uint32_t vbase = sbase + OFF_VHI * 2 +
            (uint32_t)(((p * 16 + vrow_lane) * QROW) * 2);
#pragma unroll
        for (int nt = 0; nt < 8; nt++) {
            uint32_t vh2[2];
            ldm_x2t(vh2, vbase + nt * 16);
            mma_f16(acc[nt], mh, vh2);
            mma_f16(acc[nt], ml, vh2);
        }
    }

    // ---- denominators -----------------------------------------------------
    pg  += __shfl_xor_sync(0xffffffffu, pg, 1);
    pg  += __shfl_xor_sync(0xffffffffu, pg, 2);
    pg8 += __shfl_xor_sync(0xffffffffu, pg8, 1);
    pg8 += __shfl_xor_sync(0xffffffffu, pg8, 2);

    float dqv = 0.f;
    if (lane < 16) {
        const int r = 16 * warp + lane;
        const float* zf = (const float*)(cs + OFF_Z);
#pragma unroll 8
        for (int k = 0; k < 64; k++) {
            float qv = __half2float(cs[OFF_QHI + r * QROW + k]) +
                       __half2float(cs[OFF_QLO + r * QROW + k]);
            dqv += qv * zf[k];
        }
    }
    const float dq0 = __shfl_sync(0xffffffffu, dqv, g);
    const float dq8 = __shfl_sync(0xffffffffu, dqv, g + 8);
    const float rs0 = 1.f / (pg  + dq0 + EPS_);
    const float rs1 = 1.f / (pg8 + dq8 + EPS_);

    // ---- epilogue: scale by 1/den, emit fp16 hi/lo ------------------------
    __half* obh = attn_hi + base;
    __half* obl = attn_lo + base;
#pragma unroll
    for (int nt = 0; nt < 8; nt++) {
        const int col = 8 * nt + 2 * t;
        float v0 = acc[nt][0] * rs0, v1 = acc[nt][1] * rs0;
        float v2 = acc[nt][2] * rs1, v3 = acc[nt][3] * rs1;
        float h0 = __half2float(__float2half_rn(v0));
        float h1 = __half2float(__float2half_rn(v1));
        float h2 = __half2float(__float2half_rn(v2));
        float h3 = __half2float(__float2half_rn(v3));
        *(uint32_t*)(obh + (size_t)row0 * E_ + col) = packh(h0, h1);
        *(uint32_t*)(obl + (size_t)row0 * E_ + col) = packh(v0 - h0, v1 - h1);
        *(uint32_t*)(obh + (size_t)row1 * E_ + col) = packh(h2, h3);
        *(uint32_t*)(obl + (size_t)row1 * E_ + col) = packh(v2 - h2, v3 - h3);
    }
}

// ---------------------------------------------------------------------------
// Launch
// ---------------------------------------------------------------------------
extern "C" void kernel_launch(void* const* d_in, const int* in_sizes, int n_in,
                              void* d_out, int out_size)
{
    const float* x  = (const float*)d_in[0];
    const float* Wq = (const float*)d_in[1];
    const float* Wk = (const float*)d_in[2];
    const float* Wv = (const float*)d_in[3];
    const float* Wo = (const float*)d_in[4];
    const float* bo = (const float*)d_in[5];
    float* out = (float*)d_out;

    float *phi_q, *phi_k, *vbuf, *Sb, *zb;
    __half *xhi, *xlo, *ahi, *alo, *whi;
    cudaGetSymbolAddress((void**)&phi_q, g_phi_q);
    cudaGetSymbolAddress((void**)&phi_k, g_phi_k);
    cudaGetSymbolAddress((void**)&vbuf,  g_v);
    cudaGetSymbolAddress((void**)&Sb,    g_S);
    cudaGetSymbolAddress((void**)&zb,    g_z);
    cudaGetSymbolAddress((void**)&xhi,   g_x_hi);
    cudaGetSymbolAddress((void**)&xlo,   g_x_lo);
    cudaGetSymbolAddress((void**)&ahi,   g_attn_hi);
    cudaGetSymbolAddress((void**)&alo,   g_attn_lo);
    cudaGetSymbolAddress((void**)&whi,   g_w_hi);

    const int sm_local = 2 * C_ * D_ * (int)sizeof(float);
    (void)cudaFuncSetAttribute(chunk_local_kernel,
                               cudaFuncAttributeMaxDynamicSharedMemorySize, sm_local);
    (void)cudaFuncSetAttribute(chunk_out_kernel,
                               cudaFuncAttributeMaxDynamicSharedMemorySize, CO_SMEM);
    (void)cudaFuncSetAttribute(gemm_f16split<0>,
                               cudaFuncAttributeMaxDynamicSharedMemorySize, GEMM_SMEM);
    (void)cudaFuncSetAttribute(gemm_f16split<1>,
                               cudaFuncAttributeMaxDynamicSharedMemorySize, GEMM_SMEM);

    // ---- split inputs to fp16 hi/lo (W residual discarded into scratch
    //      that chunk_out overwrites before the out-projection reads it) ----
    const int nx4 = (MTOT * E_) / 4;
    split_kernel<<<(nx4 + 255) / 256, 256>>>(x, xhi, xlo, nx4);
    const int nw4 = (E_ * E_) / 4;
    const size_t wsz = (size_t)E_ * E_;
    split_kernel<<<(nw4 + 255) / 256, 256>>>(Wq, whi + 0 * wsz, alo, nw4);
    split_kernel<<<(nw4 + 255) / 256, 256>>>(Wk, whi + 1 * wsz, alo, nw4);
    split_kernel<<<(nw4 + 255) / 256, 256>>>(Wv, whi + 2 * wsz, alo, nw4);
    split_kernel<<<(nw4 + 255) / 256, 256>>>(Wo, whi + 3 * wsz, alo, nw4);

    // ---- fused QKV projection (tensor core fp16 2-term): N = 3072 ----
    dim3 gqkv(3 * E_ / 128, MTOT / 128), gb(256);
    gemm_f16split<1><<<gqkv, gb, GEMM_SMEM>>>(xhi, xlo, whi, nullptr,
                                              phi_q, phi_k, vbuf, MTOT, 3 * E_, E_);

    // ---- chunked linear attention ----
    dim3 gc(NC_, H_, B_);
    chunk_local_kernel<<<gc, 256, sm_local>>>(phi_k, vbuf, Sb, zb);
    prefix_kernel<<<B_ * H_, 256>>>(Sb, zb);
    chunk_out_kernel<<<gc, 256, CO_SMEM>>>(phi_q, phi_k, vbuf, Sb, zb, ahi, alo);

    // ---- output projection + bias ----
    dim3 gout(E_ / 128, MTOT / 128);
    gemm_f16split<0><<<gout, gb, GEMM_SMEM>>>(ahi, alo, whi + 3 * wsz,
                                              bo, out, nullptr, nullptr, MTOT, E_, E_);
}

// round 12
// speedup vs baseline: 3.9827x; 1.0745x over previous
#include <cuda_runtime.h>
#include <cuda_fp16.h>
#include <cstdint>
#include <cstddef>

// Problem constants
#define B_   4
#define L_   4096
#define E_   1024
#define H_   16
#define D_   64
#define C_   128
#define NC_  (L_ / C_)
#define MTOT (B_ * L_)
#define EPS_ 1e-5f

// ---------------------------------------------------------------------------
// Scratch
// ---------------------------------------------------------------------------
__device__ float g_phi_q[(size_t)B_ * L_ * E_];
__device__ float g_phi_k[(size_t)B_ * L_ * E_];
__device__ float g_v    [(size_t)B_ * L_ * E_];
__device__ float g_S[(size_t)B_ * H_ * NC_ * D_ * D_];
__device__ float g_z[(size_t)B_ * H_ * NC_ * D_];

// fp16 split buffers (only the A-side residual is consumed by the GEMMs)
__device__ __half g_x_hi[(size_t)MTOT * E_];
__device__ __half g_x_lo[(size_t)MTOT * E_];
__device__ __half g_attn_hi[(size_t)MTOT * E_];
__device__ __half g_attn_lo[(size_t)MTOT * E_];
__device__ __half g_w_hi[4][(size_t)E_ * E_];   // q,k,v contiguous = [3072][1024]

// ---------------------------------------------------------------------------
// PTX helpers
// ---------------------------------------------------------------------------
__device__ __forceinline__ void mma_f16(float* c, const uint32_t* a, const uint32_t* b)
{
    asm volatile(
        "mma.sync.aligned.m16n8k16.row.col.f32.f16.f16.f32 "
        "{%0,%1,%2,%3}, {%4,%5,%6,%7}, {%8,%9}, {%0,%1,%2,%3};\n"
        : "+f"(c[0]), "+f"(c[1]), "+f"(c[2]), "+f"(c[3])
        : "r"(a[0]), "r"(a[1]), "r"(a[2]), "r"(a[3]), "r"(b[0]), "r"(b[1]));
}

__device__ __forceinline__ void ldm_x4(uint32_t* r, uint32_t addr)
{
    asm volatile("ldmatrix.sync.aligned.m8n8.x4.shared.b16 {%0,%1,%2,%3}, [%4];\n"
                 : "=r"(r[0]), "=r"(r[1]), "=r"(r[2]), "=r"(r[3]) : "r"(addr));
}
__device__ __forceinline__ void ldm_x4t(uint32_t* r, uint32_t addr)
{
    asm volatile("ldmatrix.sync.aligned.m8n8.x4.trans.shared.b16 {%0,%1,%2,%3}, [%4];\n"
                 : "=r"(r[0]), "=r"(r[1]), "=r"(r[2]), "=r"(r[3]) : "r"(addr));
}
__device__ __forceinline__ void ldm_x2t(uint32_t* r, uint32_t addr)
{
    asm volatile("ldmatrix.sync.aligned.m8n8.x2.trans.shared.b16 {%0,%1}, [%2];\n"
                 : "=r"(r[0]), "=r"(r[1]) : "r"(addr));
}
__device__ __forceinline__ uint32_t packh(float a, float b)
{
    __half2 h = __floats2half2_rn(a, b);
    return *(uint32_t*)&h;
}
__device__ __forceinline__ void cp16h(__half* dst, const __half* src)
{
    uint32_t d = (uint32_t)__cvta_generic_to_shared(dst);
    asm volatile("cp.async.cg.shared.global [%0], [%1], 16;\n" :: "r"(d), "l"(src));
}
__device__ __forceinline__ void cp_commit() { asm volatile("cp.async.commit_group;\n"); }
__device__ __forceinline__ void cp_wait1()  { asm volatile("cp.async.wait_group 1;\n"); }
__device__ __forceinline__ void cp_wait0()  { asm volatile("cp.async.wait_group 0;\n"); }

// ---------------------------------------------------------------------------
// Splits
// ---------------------------------------------------------------------------
__global__ __launch_bounds__(256)
void split_kernel(const float* __restrict__ in, __half* __restrict__ hi,
                  __half* __restrict__ lo, int n4)
{
    int i = blockIdx.x * 256 + threadIdx.x;
    if (i >= n4) return;
    float4 v = ((const float4*)in)[i];
    union { __half b[4]; uint2 u; } ph, pl;
    const float* vp = (const float*)&v;
#pragma unroll
    for (int j = 0; j < 4; j++) {
        __half hb = __float2half_rn(vp[j]);
        ph.b[j] = hb;
        pl.b[j] = __float2half_rn(vp[j] - __half2float(hb));
    }
    ((uint2*)hi)[i] = ph.u;
    ((uint2*)lo)[i] = pl.u;
}

// fused 4-weight split: blockIdx.y selects the weight; lo residual discarded
__global__ __launch_bounds__(256)
void wsplit_kernel(const float* __restrict__ w0, const float* __restrict__ w1,
                   const float* __restrict__ w2, const float* __restrict__ w3,
                   __half* __restrict__ hi_base, int n4)
{
    int i = blockIdx.x * 256 + threadIdx.x;
    if (i >= n4) return;
    const int sel = blockIdx.y;
    const float* src = (sel == 0) ? w0 : (sel == 1) ? w1 : (sel == 2) ? w2 : w3;
    __half* hi = hi_base + (size_t)sel * E_ * E_;
    float4 v = ((const float4*)src)[i];
    union { __half b[4]; uint2 u; } ph;
    ph.b[0] = __float2half_rn(v.x); ph.b[1] = __float2half_rn(v.y);
    ph.b[2] = __float2half_rn(v.z); ph.b[3] = __float2half_rn(v.w);
    ((uint2*)hi)[i] = ph.u;
}

// ---------------------------------------------------------------------------
// Tensor-core GEMM, fp16 2-term split: C = (Ahi+Alo) @ Bhi^T  (verified R10/R11)
// ---------------------------------------------------------------------------
#define SROW 40
#define STAGE_ELEMS (3 * 128 * SROW)     // Ahi, Alo, Bhi
#define GEMM_SMEM (2 * STAGE_ELEMS * 2)

template <int MODE>
__global__ __launch_bounds__(256, 2)
void gemm_f16split(const __half* __restrict__ Ahi, const __half* __restrict__ Alo,
                   const __half* __restrict__ Bhi,
                   const float* __restrict__ bias,
                   float* __restrict__ out0, float* __restrict__ out1, float* __restrict__ out2,
                   int M, int N, int K)
{
    extern __shared__ __half smem[];

    const int tid  = threadIdx.x;
    const int bm   = blockIdx.y * 128;
    const int bn   = blockIdx.x * 128;
    const int warp = tid >> 5, lane = tid & 31;
    const int wm   = (warp & 3) * 32;
    const int wn   = (warp >> 2) * 64;
    const int gid  = lane >> 2;
    const int tig  = lane & 3;

    const int KT = K / 32;

    __half* stage0 = smem;
    __half* stage1 = smem + STAGE_ELEMS;
    const uint32_t st0s = (uint32_t)__cvta_generic_to_shared(stage0);
    const uint32_t st1s = st0s + STAGE_ELEMS * 2;
    const uint32_t ALO_OFF = 128 * SROW * 2;
    const uint32_t BHI_OFF = 2 * 128 * SROW * 2;

    const int lidx = lane & 7;
    const int lmat = lane >> 3;
    int aoff[2];
#pragma unroll
    for (int mi = 0; mi < 2; mi++)
        aoff[mi] = (wm + mi * 16 + ((lmat & 1) << 3) + lidx) * SROW + ((lmat >> 1) << 3);
    int boff[4];
#pragma unroll
    for (int p = 0; p < 4; p++)
        boff[p] = (wn + p * 16 + ((lmat >> 1) << 3) + lidx) * SROW + ((lmat & 1) << 3);

    auto issue = [&](int kt, int s) {
        __half* sAh = s ? stage1 : stage0;
        __half* sAl = sAh + 128 * SROW;
        __half* sBh = sAl + 128 * SROW;
        const int kbase = kt * 32;
#pragma unroll
        for (int c = 0; c < 2; c++) {
            int q   = tid + c * 256;
            int row = q >> 2;
            int kc  = (q & 3) << 3;
            const size_t ga = (size_t)(bm + row) * K + kbase + kc;
            const size_t gb = (size_t)(bn + row) * K + kbase + kc;
            cp16h(sAh + row * SROW + kc, Ahi + ga);
            cp16h(sAl + row * SROW + kc, Alo + ga);
            cp16h(sBh + row * SROW + kc, Bhi + gb);
        }
        cp_commit();
    };

    float acc[2][8][4];
#pragma unroll
    for (int mi = 0; mi < 2; mi++)
#pragma unroll
        for (int ni = 0; ni < 8; ni++)
#pragma unroll
            for (int j = 0; j < 4; j++) acc[mi][ni][j] = 0.f;

    issue(0, 0);
    issue(1, 1);

    for (int kt = 0; kt < KT; kt++) {
        if (kt + 1 < KT) cp_wait1(); else cp_wait0();
        __syncthreads();

        const uint32_t sb = (kt & 1) ? st1s : st0s;

#pragma unroll
        for (int ks = 0; ks < 2; ks++) {
            const uint32_t kofs = (uint32_t)(ks * 16) * 2;
            uint32_t ahi[2][4], alo[2][4];
#pragma unroll
            for (int mi = 0; mi < 2; mi++) {
                const uint32_t ab = sb + (uint32_t)aoff[mi] * 2 + kofs;
                ldm_x4(ahi[mi], ab);
                ldm_x4(alo[mi], ab + ALO_OFF);
            }
#pragma unroll
            for (int p = 0; p < 4; p++) {
                uint32_t bh4[4];
                const uint32_t bb = sb + BHI_OFF + (uint32_t)boff[p] * 2 + kofs;
                ldm_x4(bh4, bb);
#pragma unroll
                for (int sub = 0; sub < 2; sub++) {
                    const uint32_t bh2[2] = { bh4[sub * 2], bh4[sub * 2 + 1] };
                    const int ni = p * 2 + sub;
#pragma unroll
                    for (int mi = 0; mi < 2; mi++) {
                        mma_f16(acc[mi][ni], ahi[mi], bh2);
                        mma_f16(acc[mi][ni], alo[mi], bh2);
                    }
                }
            }
        }
        __syncthreads();
        if (kt + 2 < KT) issue(kt + 2, kt & 1);
    }

    float* dst;
    int col_base, nOut;
    bool do_elu = false;
    if (MODE == 1) {
        const int seg = (int)blockIdx.x >> 3;
        dst = (seg == 0) ? out0 : (seg == 1) ? out1 : out2;
        col_base = ((int)blockIdx.x & 7) * 128;
        nOut = 1024;
        do_elu = (seg < 2);
    } else {
        dst = out0; col_base = bn; nOut = N;
    }

#pragma unroll
    for (int mi = 0; mi < 2; mi++) {
#pragma unroll
        for (int ni = 0; ni < 8; ni++) {
            const int row = bm + wm + mi * 16 + gid;
            const int col = col_base + wn + ni * 8 + tig * 2;
            float v0 = acc[mi][ni][0], v1 = acc[mi][ni][1];
            float v2 = acc[mi][ni][2], v3 = acc[mi][ni][3];
            if (MODE == 1) {
                if (do_elu) {
                    v0 = (v0 > 0.f) ? (v0 + 1.f) : expf(v0);
                    v1 = (v1 > 0.f) ? (v1 + 1.f) : expf(v1);
                    v2 = (v2 > 0.f) ? (v2 + 1.f) : expf(v2);
                    v3 = (v3 > 0.f) ? (v3 + 1.f) : expf(v3);
                }
            } else {
                v0 += bias[col]; v1 += bias[col + 1];
                v2 += bias[col]; v3 += bias[col + 1];
            }
            *(float2*)(dst + (size_t)row * nOut + col)       = make_float2(v0, v1);
            *(float2*)(dst + (size_t)(row + 8) * nOut + col) = make_float2(v2, v3);
        }
    }
}

// ---------------------------------------------------------------------------
// Chunk-local states — tensor-core version.
//   S_loc[d][e] = sum_t phi_k[t][d] * V[t][e]   (64x64x128 per block)
//   A = phi_k^T via ldmatrix.x4.trans; B = V via ldmatrix.x2.trans (verified map)
//   fp16 2-term on A (phi_k hi/lo), V hi only.
// 8 warps: warp (wm=warp&3)*16 M-rows x (wn=warp>>2)*32 N-cols.
// ---------------------------------------------------------------------------
#define CLROW 72
#define OFF_CKH 0
#define OFF_CKL (OFF_CKH + 128 * CLROW)
#define OFF_CVH (OFF_CKL + 128 * CLROW)
#define CL_SMEM ((OFF_CVH + 128 * CLROW) * 2)

__global__ __launch_bounds__(256, 2)
void chunk_local_tc(const float* __restrict__ pk, const float* __restrict__ vv,
                    float* __restrict__ Sloc, float* __restrict__ zloc)
{
    extern __shared__ __half cls[];
    const uint32_t sbase = (uint32_t)__cvta_generic_to_shared(cls);

    const int tid  = threadIdx.x;
    const int warp = tid >> 5, lane = tid & 31;
    const int g    = lane >> 2, t = lane & 3;
    const int lidx = lane & 7,  lmat = lane >> 3;

    const int c = blockIdx.x, h = blockIdx.y, b = blockIdx.z;
    const size_t base = ((size_t)b * L_ + (size_t)c * C_) * E_ + (size_t)h * D_;
    const float* pkb = pk + base;
    const float* vb  = vv + base;

    // load phi_k hi/lo + V hi
    for (int i = tid; i < 128 * 16; i += 256) {
        const int row = i >> 4;
        const int c4  = (i & 15) << 2;
        float4 kv = *(const float4*)(pkb + (size_t)row * E_ + c4);
        float4 wv = *(const float4*)(vb  + (size_t)row * E_ + c4);
        union { __half bx[4]; uint2 u; } ph, pl, pvx;
        const float* kp = (const float*)&kv;
#pragma unroll
        for (int j = 0; j < 4; j++) {
            __half hb = __float2half_rn(kp[j]);
            ph.bx[j] = hb;
            pl.bx[j] = __float2half_rn(kp[j] - __half2float(hb));
        }
        pvx.bx[0] = __float2half_rn(wv.x); pvx.bx[1] = __float2half_rn(wv.y);
        pvx.bx[2] = __float2half_rn(wv.z); pvx.bx[3] = __float2half_rn(wv.w);
        *(uint2*)&cls[OFF_CKH + row * CLROW + c4] = ph.u;
        *(uint2*)&cls[OFF_CKL + row * CLROW + c4] = pl.u;
        *(uint2*)&cls[OFF_CVH + row * CLROW + c4] = pvx.u;
    }
    __syncthreads();

    const int wm_ = (warp & 3) * 16;   // M (d) rows
    const int wn_ = (warp >> 2) * 32;  // N (e) cols

    float acc[4][4];
#pragma unroll
    for (int nt = 0; nt < 4; nt++)
#pragma unroll
        for (int q = 0; q < 4; q++) acc[nt][q] = 0.f;

#pragma unroll
    for (int ks = 0; ks < 8; ks++) {
        const int k0 = ks * 16;
        // A = phi_k^T: trans ldmatrix from phi_k[t][d] storage
        const uint32_t arow = (uint32_t)(k0 + ((lmat >> 1) << 3) + lidx);
        const uint32_t acol = (uint32_t)(wm_ + ((lmat & 1) << 3));
        const uint32_t aaddr = sbase + (uint32_t)((OFF_CKH + arow * CLROW + acol) * 2);
        uint32_t ah[4], al[4];
        ldm_x4t(ah, aaddr);
        ldm_x4t(al, aaddr + (OFF_CKL - OFF_CKH) * 2);

        const uint32_t vaddr0 = sbase +
            (uint32_t)((OFF_CVH + (k0 + (lane & 15)) * CLROW + wn_) * 2);
#pragma unroll
        for (int nt = 0; nt < 4; nt++) {
            uint32_t bh2[2];
            ldm_x2t(bh2, vaddr0 + nt * 16);
            mma_f16(acc[nt], ah, bh2);
            mma_f16(acc[nt], al, bh2);
        }
    }

    // write S_loc (fp32)
    float* Sout = Sloc + ((((size_t)b * H_ + h) * NC_ + c) * D_ * D_);
    const int row0 = wm_ + g, row1 = row0 + 8;
#pragma unroll
    for (int nt = 0; nt < 4; nt++) {
        const int col = wn_ + nt * 8 + 2 * t;
        *(float2*)(Sout + (size_t)row0 * D_ + col) = make_float2(acc[nt][0], acc[nt][1]);
        *(float2*)(Sout + (size_t)row1 * D_ + col) = make_float2(acc[nt][2], acc[nt][3]);
    }

    // z_loc = colsum phi_k (hi + lo)
    if (tid < D_) {
        float s = 0.f;
#pragma unroll 8
        for (int r = 0; r < C_; r++)
            s += __half2float(cls[OFF_CKH + r * CLROW + tid]) +
                 __half2float(cls[OFF_CKL + r * CLROW + tid]);
        zloc[(((size_t)b * H_ + h) * NC_ + c) * D_ + tid] = s;
    }
}

// ---------------------------------------------------------------------------
// Exclusive prefix — one element-scan per thread, coalesced across chunks.
// grid (B_*H_, 16), 256 threads.
// ---------------------------------------------------------------------------
__global__ __launch_bounds__(256)
void prefix_kernel(float* __restrict__ S, float* __restrict__ z)
{
    const int bh = blockIdx.x;
    const int i  = blockIdx.y * 256 + threadIdx.x;   // 0..4095
    float* Sb = S + (size_t)bh * NC_ * D_ * D_;

    float run = 0.f;
#pragma unroll
    for (int c = 0; c < NC_; c++) {
        float* p = Sb + (size_t)c * D_ * D_ + i;
        float loc = *p;
        *p = run;
        run += loc;
    }

    if (blockIdx.y == 0 && threadIdx.x < D_) {
        float* zb = z + (size_t)bh * NC_ * D_;
        float zr = 0.f;
#pragma unroll
        for (int c = 0; c < NC_; c++) {
            float loc = zb[(size_t)c * D_ + threadIdx.x];
            zb[(size_t)c * D_ + threadIdx.x] = zr;
            zr += loc;
        }
    }
}

// ---------------------------------------------------------------------------
// Chunk output — verified R11 (fp16 2-term, causal tile skip)
// ---------------------------------------------------------------------------
#define QROW 72
#define OFF_QHI 0
#define OFF_QLO (OFF_QHI + 128 * QROW)
#define OFF_KHI (OFF_QLO + 128 * QROW)
#define OFF_VHI (OFF_KHI + 128 * QROW)
#define OFF_STHI (OFF_VHI + 128 * QROW)
#define OFF_Z    (OFF_STHI + 64 * QROW)
#define CO_SMEM ((OFF_Z + 128) * 2)

__global__ __launch_bounds__(256, 2)
void chunk_out_kernel(const float* __restrict__ pq, const float* __restrict__ pk,
                      const float* __restrict__ vv, const float* __restrict__ S,
                      const float* __restrict__ z,
                      __half* __restrict__ attn_hi,
                      __half* __restrict__ attn_lo)
{
    extern __shared__ __half cs[];
    const uint32_t sbase = (uint32_t)__cvta_generic_to_shared(cs);

    const int tid  = threadIdx.x;
    const int warp = tid >> 5, lane = tid & 31;
    const int g    = lane >> 2, t = lane & 3;
    const int lidx = lane & 7,  lmat = lane >> 3;

    const int c = blockIdx.x, h = blockIdx.y, b = blockIdx.z;
    const size_t base = ((size_t)b * L_ + (size_t)c * C_) * E_ + (size_t)h * D_;
    const float* pqb = pq + base;
    const float* pkb = pk + base;
    const float* vb  = vv + base;

    for (int i = tid; i < 128 * 16; i += 256) {
        const int row = i >> 4;
        const int c4  = (i & 15) << 2;
        float4 qv = *(const float4*)(pqb + (size_t)row * E_ + c4);
        float4 kv = *(const float4*)(pkb + (size_t)row * E_ + c4);
        float4 wv = *(const float4*)(vb  + (size_t)row * E_ + c4);
        union { __half bx[4]; uint2 u; } ph, pl, pkx, pvx;
        const float* qp = (const float*)&qv;
#pragma unroll
        for (int j = 0; j < 4; j++) {
            __half hb = __float2half_rn(qp[j]);
            ph.bx[j] = hb;
            pl.bx[j] = __float2half_rn(qp[j] - __half2float(hb));
        }
        pkx.bx[0] = __float2half_rn(kv.x); pkx.bx[1] = __float2half_rn(kv.y);
        pkx.bx[2] = __float2half_rn(kv.z); pkx.bx[3] = __float2half_rn(kv.w);
        pvx.bx[0] = __float2half_rn(wv.x); pvx.bx[1] = __float2half_rn(wv.y);
        pvx.bx[2] = __float2half_rn(wv.z); pvx.bx[3] = __float2half_rn(wv.w);
        *(uint2*)&cs[OFF_QHI + row * QROW + c4] = ph.u;
        *(uint2*)&cs[OFF_QLO + row * QROW + c4] = pl.u;
        *(uint2*)&cs[OFF_KHI + row * QROW + c4] = pkx.u;
        *(uint2*)&cs[OFF_VHI + row * QROW + c4] = pvx.u;
    }
    {
        const float* Sb = S + (((size_t)b * H_ + h) * NC_ + c) * D_ * D_;
        for (int i = tid; i < 64 * 16; i += 256) {
            const int r  = i >> 4;
            const int c4 = (i & 15) << 2;
            float4 sv = *(const float4*)(Sb + (size_t)r * D_ + c4);
            const float* sp = (const float*)&sv;
#pragma unroll
            for (int j = 0; j < 4; j++)
                cs[OFF_STHI + (c4 + j) * QROW + r] = __float2half_rn(sp[j]);
        }
        if (tid < 64) {
            const float* zbp = z + (((size_t)b * H_ + h) * NC_ + c) * D_;
            ((float*)(cs + OFF_Z))[tid] = zbp[tid];
        }
    }
    __syncthreads();

    const uint32_t aoff_b =
        (uint32_t)(((16 * warp + ((lmat & 1) << 3) + lidx) * QROW + ((lmat >> 1) << 3)) * 2);
    uint32_t aqh[4][4], aql[4][4];
#pragma unroll
    for (int ks = 0; ks < 4; ks++) {
        const uint32_t qa = sbase + OFF_QHI * 2 + aoff_b + ks * 32;
        ldm_x4(aqh[ks], qa);
        ldm_x4(aql[ks], qa + (OFF_QLO - OFF_QHI) * 2);
    }

    float acc[8][4];
#pragma unroll
    for (int nt = 0; nt < 8; nt++)
#pragma unroll
        for (int q = 0; q < 4; q++) acc[nt][q] = 0.f;

#pragma unroll
    for (int ks = 0; ks < 4; ks++) {
#pragma unroll
        for (int p4 = 0; p4 < 4; p4++) {
            const uint32_t bb = sbase + OFF_STHI * 2 +
                (uint32_t)(((p4 * 16 + ((lmat >> 1) << 3) + lidx) * QROW + ((lmat & 1) << 3)) * 2)
                + ks * 32;
            uint32_t bh4[4];
            ldm_x4(bh4, bb);
#pragma unroll
            for (int sub = 0; sub < 2; sub++) {
                const uint32_t bh2[2] = { bh4[sub * 2], bh4[sub * 2 + 1] };
                mma_f16(acc[2 * p4 + sub], aqh[ks], bh2);
                mma_f16(acc[2 * p4 + sub], aql[ks], bh2);
            }
        }
    }

    const int row0 = 16 * warp + g;
    const int row1 = row0 + 8;
    float pg = 0.f, pg8 = 0.f;
    const uint32_t vrow_lane = (uint32_t)(lane & 15);

    for (int p = 0; p <= warp; p++) {
        float mC2[2][4];
#pragma unroll
        for (int sub = 0; sub < 2; sub++)
#pragma unroll
            for (int q = 0; q < 4; q++) mC2[sub][q] = 0.f;

#pragma unroll
        for (int ks = 0; ks < 4; ks++) {
            const uint32_t bb = sbase + OFF_KHI * 2 +
                (uint32_t)(((p * 16 + ((lmat >> 1) << 3) + lidx) * QROW + ((lmat & 1) << 3)) * 2)
                + ks * 32;
            uint32_t bh4[4];
            ldm_x4(bh4, bb);
#pragma unroll
            for (int sub = 0; sub < 2; sub++) {
                const uint32_t bh2[2] = { bh4[sub * 2], bh4[sub * 2 + 1] };
                mma_f16(mC2[sub], aqh[ks], bh2);
                mma_f16(mC2[sub], aql[ks], bh2);
            }
        }

        if (p == warp) {
#pragma unroll
            for (int sub = 0; sub < 2; sub++) {
                const int c0 = 16 * p + 8 * sub + 2 * t;
                if (c0 > row0)     mC2[sub][0] = 0.f;
                if (c0 + 1 > row0) mC2[sub][1] = 0.f;
                if (c0 > row1)     mC2[sub][2] = 0.f;
                if (c0 + 1 > row1) mC2[sub][3] = 0.f;
            }
        }
        pg  += mC2[0][0] + mC2[0][1] + mC2[1][0] + mC2[1][1];
        pg8 += mC2[0][2] + mC2[0][3] + mC2[1][2] + mC2[1][3];

        uint32_t mh[4], ml[4];
#pragma unroll
        for (int q = 0; q < 4; q++) {
            const int sub = q >> 1;
            const int lohalf = (q & 1) * 2;
            float v0 = mC2[sub][lohalf], v1 = mC2[sub][lohalf + 1];
            float h0 = __half2float(__float2half_rn(v0));
            float h1 = __half2float(__float2half_rn(v1));
            mh[q] = packh(h0, h1);
            ml[q] = packh(v0 - h0, v1 - h1);
        }

        const uint32_t vbase = sbase + OFF_VHI * 2 +
            (uint32_t)(((p * 16 + vrow_lane) * QROW) * 2);
#pragma unroll
        for (int nt = 0; nt < 8; nt++) {
            uint32_t vh2[2];
            ldm_x2t(vh2, vbase + nt * 16);
            mma_f16(acc[nt], mh, vh2);
            mma_f16(acc[nt], ml, vh2);
        }
    }

    pg  += __shfl_xor_sync(0xffffffffu, pg, 1);
    pg  += __shfl_xor_sync(0xffffffffu, pg, 2);
    pg8 += __shfl_xor_sync(0xffffffffu, pg8, 1);
    pg8 += __shfl_xor_sync(0xffffffffu, pg8, 2);

    float dqv = 0.f;
    if (lane < 16) {
        const int r = 16 * warp + lane;
        const float* zf = (const float*)(cs + OFF_Z);
#pragma unroll 8
        for (int k = 0; k < 64; k++) {
            float qv = __half2float(cs[OFF_QHI + r * QROW + k]) +
                       __half2float(cs[OFF_QLO + r * QROW + k]);
            dqv += qv * zf[k];
        }
    }
    const float dq0 = __shfl_sync(0xffffffffu, dqv, g);
    const float dq8 = __shfl_sync(0xffffffffu, dqv, g + 8);
    const float rs0 = 1.f / (pg  + dq0 + EPS_);
    const float rs1 = 1.f / (pg8 + dq8 + EPS_);

    __half* obh = attn_hi + base;
    __half* obl = attn_lo + base;
#pragma unroll
    for (int nt = 0; nt < 8; nt++) {
        const int col = 8 * nt + 2 * t;
        float v0 = acc[nt][0] * rs0, v1 = acc[nt][1] * rs0;
        float v2 = acc[nt][2] * rs1, v3 = acc[nt][3] * rs1;
        float h0 = __half2float(__float2half_rn(v0));
        float h1 = __half2float(__float2half_rn(v1));
        float h2 = __half2float(__float2half_rn(v2));
        float h3 = __half2float(__float2half_rn(v3));
        *(uint32_t*)(obh + (size_t)row0 * E_ + col) = packh(h0, h1);
        *(uint32_t*)(obl + (size_t)row0 * E_ + col) = packh(v0 - h0, v1 - h1);
        *(uint32_t*)(obh + (size_t)row1 * E_ + col) = packh(h2, h3);
        *(uint32_t*)(obl + (size_t)row1 * E_ + col) = packh(v2 - h2, v3 - h3);
    }
}

// ---------------------------------------------------------------------------
// Launch
// ---------------------------------------------------------------------------
extern "C" void kernel_launch(void* const* d_in, const int* in_sizes, int n_in,
                              void* d_out, int out_size)
{
    const float* x  = (const float*)d_in[0];
    const float* Wq = (const float*)d_in[1];
    const float* Wk = (const float*)d_in[2];
    const float* Wv = (const float*)d_in[3];
    const float* Wo = (const float*)d_in[4];
    const float* bo = (const float*)d_in[5];
    float* out = (float*)d_out;

    float *phi_q, *phi_k, *vbuf, *Sb, *zb;
    __half *xhi, *xlo, *ahi, *alo, *whi;
    cudaGetSymbolAddress((void**)&phi_q, g_phi_q);
    cudaGetSymbolAddress((void**)&phi_k, g_phi_k);
    cudaGetSymbolAddress((void**)&vbuf,  g_v);
    cudaGetSymbolAddress((void**)&Sb,    g_S);
    cudaGetSymbolAddress((void**)&zb,    g_z);
    cudaGetSymbolAddress((void**)&xhi,   g_x_hi);
    cudaGetSymbolAddress((void**)&xlo,   g_x_lo);
    cudaGetSymbolAddress((void**)&ahi,   g_attn_hi);
    cudaGetSymbolAddress((void**)&alo,   g_attn_lo);
    cudaGetSymbolAddress((void**)&whi,   g_w_hi);

    (void)cudaFuncSetAttribute(chunk_local_tc,
                               cudaFuncAttributeMaxDynamicSharedMemorySize, CL_SMEM);
    (void)cudaFuncSetAttribute(chunk_out_kernel,
                               cudaFuncAttributeMaxDynamicSharedMemorySize, CO_SMEM);
    (void)cudaFuncSetAttribute(gemm_f16split<0>,
                               cudaFuncAttributeMaxDynamicSharedMemorySize, GEMM_SMEM);
    (void)cudaFuncSetAttribute(gemm_f16split<1>,
                               cudaFuncAttributeMaxDynamicSharedMemorySize, GEMM_SMEM);

    // ---- splits ----
    const int nx4 = (MTOT * E_) / 4;
    split_kernel<<<(nx4 + 255) / 256, 256>>>(x, xhi, xlo, nx4);
    const int nw4 = (E_ * E_) / 4;
    const size_t wsz = (size_t)E_ * E_;
    dim3 gws((nw4 + 255) / 256, 4);
    wsplit_kernel<<<gws, 256>>>(Wq, Wk, Wv, Wo, whi, nw4);

    // ---- fused QKV projection (tensor core fp16 2-term): N = 3072 ----
    dim3 gqkv(3 * E_ / 128, MTOT / 128), gb(256);
    gemm_f16split<1><<<gqkv, gb, GEMM_SMEM>>>(xhi, xlo, whi, nullptr,
                                              phi_q, phi_k, vbuf, MTOT, 3 * E_, E_);

    // ---- chunked linear attention ----
    dim3 gc(NC_, H_, B_);
    chunk_local_tc<<<gc, 256, CL_SMEM>>>(phi_k, vbuf, Sb, zb);
    dim3 gp(B_ * H_, 16);
    prefix_kernel<<<gp, 256>>>(Sb, zb);
    chunk_out_kernel<<<gc, 256, CO_SMEM>>>(phi_q, phi_k, vbuf, Sb, zb, ahi, alo);

    // ---- output projection + bias ----
    dim3 gout(E_ / 128, MTOT / 128);
    gemm_f16split<0><<<gout, gb, GEMM_SMEM>>>(ahi, alo, whi + 3 * wsz,
                                              bo, out, nullptr, nullptr, MTOT, E_, E_);
}